// round 1
// baseline (speedup 1.0000x reference)
#include <cuda_runtime.h>
#include <math.h>

#define HW    4096
#define CDIM  256
#define BATCH 8
#define NBH   64     // B*HEADS
#define DH    64     // DIM_HEAD

// ---------------- scratch (device globals; no runtime allocation) ----------
__device__ float g_ctx[BATCH * CDIM * HW];        // layernormed context
__device__ float g_qs [BATCH * CDIM * HW];        // layernormed query_source
__device__ float g_kv [BATCH * 1024 * HW];        // w_kv output (k then v per batch)
__device__ float g_q  [BATCH * 512  * HW];        // w_q output (l2-normalized in place)
__device__ float g_att[BATCH * 512  * HW];        // attention output, (b, inner, pix)
__device__ float g_y  [BATCH * CDIM * HW];        // w_out output
__device__ float g_qprobe[NBH * DH];
__device__ float g_rowabs[NBH * DH * 64];         // [bh][d][h]
__device__ float g_colabs[NBH * DH * 64];         // [bh][d][w]
__device__ int   g_idxh[NBH * 8];
__device__ int   g_idxw[NBH * 8];
__device__ float g_ksel[NBH * 64 * DH];           // [bh][j][d]
__device__ float g_vsel[NBH * 64 * DH];

// ---------------- zero scratch reductions ----------------------------------
__global__ void zero_kernel() {
    int i = blockIdx.x * 256 + threadIdx.x;
    if (i < NBH * DH) g_qprobe[i] = 0.f;
    if (i < NBH * DH * 64) { g_rowabs[i] = 0.f; g_colabs[i] = 0.f; }
}

// ---------------- channel layernorm (per pixel over 256 channels) ----------
// blockDim (32,8); each block = 32 consecutive pixels of one batch image.
__global__ void ln_kernel(const float* __restrict__ x,
                          const float* __restrict__ gw,
                          const float* __restrict__ bw,
                          int outsel) {
    float* out = outsel ? g_qs : g_ctx;
    int tx = threadIdx.x, ty = threadIdx.y;
    int gp = blockIdx.x * 32 + tx;          // global pixel across batch
    int bidx = gp >> 12;
    int p = gp & (HW - 1);
    size_t base = (size_t)bidx * CDIM * HW + p;

    float vals[32];
    float s = 0.f, s2 = 0.f;
#pragma unroll
    for (int i = 0; i < 32; i++) {
        int c = ty + i * 8;
        float v = x[base + (size_t)c * HW];
        vals[i] = v; s += v; s2 += v * v;
    }
    __shared__ float rs[8][32], rs2[8][32];
    rs[ty][tx] = s; rs2[ty][tx] = s2;
    __syncthreads();
    for (int st = 4; st > 0; st >>= 1) {
        if (ty < st) { rs[ty][tx] += rs[ty + st][tx]; rs2[ty][tx] += rs2[ty + st][tx]; }
        __syncthreads();
    }
    float mean = rs[0][tx] * (1.0f / CDIM);
    float var  = rs2[0][tx] * (1.0f / CDIM) - mean * mean;
    float inv  = rsqrtf(var + 1e-5f);
#pragma unroll
    for (int i = 0; i < 32; i++) {
        int c = ty + i * 8;
        out[base + (size_t)c * HW] = (vals[i] - mean) * inv * gw[c] + bw[c];
    }
}

// ---------------- final: LN(g_y) * gamma + query_source -> d_out -----------
__global__ void final_kernel(const float* __restrict__ qsrc,
                             const float* __restrict__ gw,
                             const float* __restrict__ bw,
                             const float* __restrict__ gamma,
                             float* __restrict__ out) {
    int tx = threadIdx.x, ty = threadIdx.y;
    int gp = blockIdx.x * 32 + tx;
    int bidx = gp >> 12;
    int p = gp & (HW - 1);
    size_t base = (size_t)bidx * CDIM * HW + p;

    float vals[32];
    float s = 0.f, s2 = 0.f;
#pragma unroll
    for (int i = 0; i < 32; i++) {
        int c = ty + i * 8;
        float v = g_y[base + (size_t)c * HW];
        vals[i] = v; s += v; s2 += v * v;
    }
    __shared__ float rs[8][32], rs2[8][32];
    rs[ty][tx] = s; rs2[ty][tx] = s2;
    __syncthreads();
    for (int st = 4; st > 0; st >>= 1) {
        if (ty < st) { rs[ty][tx] += rs[ty + st][tx]; rs2[ty][tx] += rs2[ty + st][tx]; }
        __syncthreads();
    }
    float mean = rs[0][tx] * (1.0f / CDIM);
    float var  = rs2[0][tx] * (1.0f / CDIM) - mean * mean;
    float inv  = rsqrtf(var + 1e-5f);
    float gm = gamma[0];
#pragma unroll
    for (int i = 0; i < 32; i++) {
        int c = ty + i * 8;
        float ln = (vals[i] - mean) * inv * gw[c] + bw[c];
        out[base + (size_t)c * HW] = gm * ln + qsrc[base + (size_t)c * HW];
    }
}

// ---------------- batched SGEMM: C[b] = A(MxK) * X[b](KxN), N=4096 ---------
// 128x128 tile, BK=8, 256 threads, 8x8 per thread.
__global__ void __launch_bounds__(256)
sgemm_kernel(const float* __restrict__ A, int M, int K, int sel) {
    const float* Bp; float* Cp;
    if (sel == 0)      { Bp = g_ctx; Cp = g_kv; }
    else if (sel == 1) { Bp = g_qs;  Cp = g_q;  }
    else               { Bp = g_att; Cp = g_y;  }
    Bp += (size_t)blockIdx.z * K * HW;
    Cp += (size_t)blockIdx.z * M * HW;

    __shared__ float As[8][128];
    __shared__ float Bs[8][128];

    int m0 = blockIdx.y * 128, n0 = blockIdx.x * 128;
    int tid = threadIdx.x;
    int arow = tid >> 1, acol = (tid & 1) * 4;
    int brow = tid >> 5, bcol = (tid & 31) * 4;
    int ty = tid >> 4, tx = tid & 15;

    float acc[8][8] = {};
    for (int k0 = 0; k0 < K; k0 += 8) {
        float4 a = *(const float4*)(A + (size_t)(m0 + arow) * K + k0 + acol);
        As[acol + 0][arow] = a.x; As[acol + 1][arow] = a.y;
        As[acol + 2][arow] = a.z; As[acol + 3][arow] = a.w;
        float4 b = *(const float4*)(Bp + (size_t)(k0 + brow) * HW + n0 + bcol);
        *(float4*)(&Bs[brow][bcol]) = b;
        __syncthreads();
#pragma unroll
        for (int k = 0; k < 8; k++) {
            float ra[8], rb[8];
#pragma unroll
            for (int i = 0; i < 8; i++) ra[i] = As[k][ty * 8 + i];
#pragma unroll
            for (int j = 0; j < 8; j++) rb[j] = Bs[k][tx * 8 + j];
#pragma unroll
            for (int i = 0; i < 8; i++)
#pragma unroll
                for (int j = 0; j < 8; j++)
                    acc[i][j] += ra[i] * rb[j];
        }
        __syncthreads();
    }
#pragma unroll
    for (int i = 0; i < 8; i++) {
#pragma unroll
        for (int j = 0; j < 8; j += 4) {
            float4 v = make_float4(acc[i][j], acc[i][j+1], acc[i][j+2], acc[i][j+3]);
            *(float4*)(Cp + (size_t)(m0 + ty * 8 + i) * HW + n0 + tx * 8 + j) = v;
        }
    }
}

// ---------------- l2norm q (in place) + q_probe accumulation ---------------
// blockDim (32,8); 128 blocks per bh.
__global__ void l2q_kernel() {
    int tx = threadIdx.x, ty = threadIdx.y;
    int bh = blockIdx.x >> 7;
    int pix = (blockIdx.x & 127) * 32 + tx;
    size_t base = (size_t)bh * 64 * HW + pix;

    float v[8]; float s = 0.f;
#pragma unroll
    for (int i = 0; i < 8; i++) {
        int d = ty + i * 8;
        v[i] = g_q[base + (size_t)d * HW];
        s += v[i] * v[i];
    }
    __shared__ float rs[8][32];
    rs[ty][tx] = s; __syncthreads();
    for (int st = 4; st > 0; st >>= 1) { if (ty < st) rs[ty][tx] += rs[ty + st][tx]; __syncthreads(); }
    float n = sqrtf(rs[0][tx]);
    float inv = 1.0f / fmaxf(n, 1e-12f);
#pragma unroll
    for (int i = 0; i < 8; i++) {
        int d = ty + i * 8;
        float qn = v[i] * inv;
        g_q[base + (size_t)d * HW] = qn;
        float r = qn;
#pragma unroll
        for (int o = 16; o > 0; o >>= 1) r += __shfl_down_sync(0xffffffffu, r, o);
        if (tx == 0) atomicAdd(&g_qprobe[bh * 64 + d], r);
    }
}

// ---------------- l2norm k (in place) + row/col |k| sums -------------------
__global__ void l2k_kernel() {
    int tx = threadIdx.x, ty = threadIdx.y;
    int bh = blockIdx.x >> 7;
    int pixb = (blockIdx.x & 127) * 32;
    int pix = pixb + tx;
    int b = bh >> 3, head = bh & 7;
    size_t cbase = (size_t)(b * 16 + head) * 64 * HW;   // k channel base in g_kv
    int h = pix >> 6, w = pix & 63;

    float v[8]; float s = 0.f;
#pragma unroll
    for (int i = 0; i < 8; i++) {
        int d = ty + i * 8;
        v[i] = g_kv[cbase + (size_t)d * HW + pix];
        s += v[i] * v[i];
    }
    __shared__ float rs[8][32];
    rs[ty][tx] = s; __syncthreads();
    for (int st = 4; st > 0; st >>= 1) { if (ty < st) rs[ty][tx] += rs[ty + st][tx]; __syncthreads(); }
    float n = sqrtf(rs[0][tx]);
    float inv = 1.0f / fmaxf(n, 1e-12f);
#pragma unroll
    for (int i = 0; i < 8; i++) {
        int d = ty + i * 8;
        float kn = v[i] * inv;
        g_kv[cbase + (size_t)d * HW + pix] = kn;
        float a = fabsf(kn);
        float r = a;
#pragma unroll
        for (int o = 16; o > 0; o >>= 1) r += __shfl_down_sync(0xffffffffu, r, o);
        if (tx == 0) atomicAdd(&g_rowabs[bh * 4096 + d * 64 + h], r);
        atomicAdd(&g_colabs[bh * 4096 + d * 64 + w], a);
    }
}

// ---------------- scores + top-8 selection ---------------------------------
__global__ void score_kernel() {
    int bh = blockIdx.x;
    int t = threadIdx.x;    // 64 threads
    __shared__ float qp[64], sc[64];
    qp[t] = g_qprobe[bh * 64 + t];
    __syncthreads();

    float s = 0.f;
    for (int d = 0; d < 64; d++) s += qp[d] * g_rowabs[bh * 4096 + d * 64 + t];
    sc[t] = s;
    __syncthreads();
    if (t == 0) {
        for (int it = 0; it < 8; it++) {
            int best = 0; float bv = sc[0];
            for (int h = 1; h < 64; h++) if (sc[h] > bv) { bv = sc[h]; best = h; }
            g_idxh[bh * 8 + it] = best; sc[best] = -3e38f;
        }
    }
    __syncthreads();

    float s2 = 0.f;
    for (int d = 0; d < 64; d++) s2 += qp[d] * g_colabs[bh * 4096 + d * 64 + t];
    sc[t] = s2;
    __syncthreads();
    if (t == 0) {
        for (int it = 0; it < 8; it++) {
            int best = 0; float bv = sc[0];
            for (int w = 1; w < 64; w++) if (sc[w] > bv) { bv = sc[w]; best = w; }
            g_idxw[bh * 8 + it] = best; sc[best] = -3e38f;
        }
    }
}

// ---------------- gather selected K/V into dense [bh][64][64] --------------
__global__ void gather_kernel() {
    int bh = blockIdx.x;
    int b = bh >> 3, head = bh & 7;
    size_t kc = (size_t)(b * 16 + head) * 64 * HW;
    size_t vc = (size_t)(b * 16 + 8 + head) * 64 * HW;
    __shared__ int ih[8], iw[8];
    if (threadIdx.x < 8) ih[threadIdx.x] = g_idxh[bh * 8 + threadIdx.x];
    else if (threadIdx.x < 16) iw[threadIdx.x - 8] = g_idxw[bh * 8 + threadIdx.x - 8];
    __syncthreads();
    for (int t = threadIdx.x; t < 4096; t += 256) {
        int j = t >> 6, d = t & 63;
        int r = j >> 3, c = j & 7;
        int pix = ih[r] * 64 + iw[c];
        g_ksel[bh * 4096 + t] = g_kv[kc + (size_t)d * HW + pix];
        g_vsel[bh * 4096 + t] = g_kv[vc + (size_t)d * HW + pix];
    }
}

// ---------------- attention: 4096 queries x 64 kv per head -----------------
// grid (32, 64), 128 threads; one thread per query pixel.
__global__ void __launch_bounds__(128)
attn_kernel() {
    __shared__ float ks[64 * 64];
    __shared__ float vs[64 * 64];
    int bh = blockIdx.y;
    int pix = blockIdx.x * 128 + threadIdx.x;

    const float4* kg = (const float4*)&g_ksel[bh * 4096];
    const float4* vg = (const float4*)&g_vsel[bh * 4096];
    float4* ks4 = (float4*)ks; float4* vs4 = (float4*)vs;
    for (int i = threadIdx.x; i < 1024; i += 128) { ks4[i] = kg[i]; vs4[i] = vg[i]; }
    __syncthreads();

    size_t qb = (size_t)bh * 64 * HW + pix;
    float sim[64];
#pragma unroll
    for (int j = 0; j < 64; j++) sim[j] = 0.f;

    for (int dc = 0; dc < 64; dc += 16) {
        float q0[16];
#pragma unroll
        for (int i = 0; i < 16; i++) q0[i] = g_q[qb + (size_t)(dc + i) * HW];
#pragma unroll
        for (int j = 0; j < 64; j++) {
            const float4* kr = (const float4*)&ks[j * 64 + dc];
#pragma unroll
            for (int i4 = 0; i4 < 4; i4++) {
                float4 kvv = kr[i4];
                sim[j] += q0[i4*4+0]*kvv.x + q0[i4*4+1]*kvv.y
                        + q0[i4*4+2]*kvv.z + q0[i4*4+3]*kvv.w;
            }
        }
    }
    // softmax over 64 kv
    float mx = sim[0];
#pragma unroll
    for (int j = 1; j < 64; j++) mx = fmaxf(mx, sim[j]);
    float sum = 0.f;
#pragma unroll
    for (int j = 0; j < 64; j++) { sim[j] = expf(sim[j] - mx); sum += sim[j]; }
    float invs = 1.0f / sum;

    size_t ob = (size_t)bh * 64 * HW + pix;
    for (int dc = 0; dc < 64; dc += 32) {
        float acc[32];
#pragma unroll
        for (int i = 0; i < 32; i++) acc[i] = 0.f;
#pragma unroll
        for (int j = 0; j < 64; j++) {
            const float4* vr = (const float4*)&vs[j * 64 + dc];
            float p = sim[j];
#pragma unroll
            for (int i4 = 0; i4 < 8; i4++) {
                float4 vv = vr[i4];
                acc[i4*4+0] += p * vv.x; acc[i4*4+1] += p * vv.y;
                acc[i4*4+2] += p * vv.z; acc[i4*4+3] += p * vv.w;
            }
        }
#pragma unroll
        for (int i = 0; i < 32; i++)
            g_att[ob + (size_t)(dc + i) * HW] = acc[i] * invs;
    }
}

// ---------------- launch ----------------------------------------------------
extern "C" void kernel_launch(void* const* d_in, const int* in_sizes, int n_in,
                              void* d_out, int out_size) {
    const float* query_source = (const float*)d_in[0];
    const float* context      = (const float*)d_in[1];
    const float* cn_g = (const float*)d_in[2];
    const float* cn_b = (const float*)d_in[3];
    const float* qn_g = (const float*)d_in[4];
    const float* qn_b = (const float*)d_in[5];
    const float* on_g = (const float*)d_in[6];
    const float* on_b = (const float*)d_in[7];
    const float* w_kv  = (const float*)d_in[8];
    const float* w_q   = (const float*)d_in[9];
    const float* w_out = (const float*)d_in[10];
    const float* gamma = (const float*)d_in[11];
    float* out = (float*)d_out;

    dim3 lnb(32, 8);

    zero_kernel<<<1024, 256>>>();
    ln_kernel<<<1024, lnb>>>(context, cn_g, cn_b, 0);
    ln_kernel<<<1024, lnb>>>(query_source, qn_g, qn_b, 1);

    sgemm_kernel<<<dim3(32, 8, 8), 256>>>(w_kv, 1024, 256, 0);
    sgemm_kernel<<<dim3(32, 4, 8), 256>>>(w_q, 512, 256, 1);

    l2q_kernel<<<8192, lnb>>>();
    l2k_kernel<<<8192, lnb>>>();

    score_kernel<<<64, 64>>>();
    gather_kernel<<<64, 256>>>();

    attn_kernel<<<dim3(32, 64), 128>>>();

    sgemm_kernel<<<dim3(32, 2, 8), 256>>>(w_out, 256, 512, 2);

    final_kernel<<<1024, lnb>>>(query_source, on_g, on_b, gamma, out);
}

// round 2
// speedup vs baseline: 1.8609x; 1.8609x over previous
#include <cuda_runtime.h>
#include <math.h>
#include <stdint.h>

#define HW    4096
#define CDIM  256
#define BATCH 8
#define NBH   64     // B*HEADS
#define DH    64     // DIM_HEAD

// ---------------- scratch (device globals; no runtime allocation) ----------
__device__ float g_ctx[BATCH * CDIM * HW];        // layernormed context (tf32-rounded)
__device__ float g_qs [BATCH * CDIM * HW];        // layernormed query_source (tf32-rounded)
__device__ float g_kv [BATCH * 1024 * HW];        // w_kv output (k then v per batch)
__device__ float g_q  [BATCH * 512  * HW];        // w_q output (l2-normalized in place)
__device__ float g_att[BATCH * 512  * HW];        // attention output (tf32-rounded)
__device__ float g_y  [BATCH * CDIM * HW];        // w_out output
__device__ float g_qprobe[NBH * DH];
__device__ float g_rowabs[NBH * DH * 64];         // [bh][d][h]
__device__ float g_colabs[NBH * DH * 64];         // [bh][d][w]
__device__ int   g_idxh[NBH * 8];
__device__ int   g_idxw[NBH * 8];
__device__ float g_ksel[NBH * 64 * DH];           // [bh][j][d]
__device__ float g_vsel[NBH * 64 * DH];

__device__ __forceinline__ float tf32r(float x) {
    uint32_t u;
    asm("cvt.rna.tf32.f32 %0, %1;" : "=r"(u) : "f"(x));
    return __uint_as_float(u);
}
__device__ __forceinline__ uint32_t tf32u(float x) {
    uint32_t u;
    asm("cvt.rna.tf32.f32 %0, %1;" : "=r"(u) : "f"(x));
    return u;
}

// ---------------- zero scratch reductions ----------------------------------
__global__ void zero_kernel() {
    int i = blockIdx.x * 256 + threadIdx.x;
    if (i < NBH * DH) g_qprobe[i] = 0.f;
    if (i < NBH * DH * 64) { g_rowabs[i] = 0.f; g_colabs[i] = 0.f; }
}

// ---------------- channel layernorm (per pixel over 256 channels) ----------
__global__ void ln_kernel(const float* __restrict__ x,
                          const float* __restrict__ gw,
                          const float* __restrict__ bw,
                          int outsel) {
    float* out = outsel ? g_qs : g_ctx;
    int tx = threadIdx.x, ty = threadIdx.y;
    int gp = blockIdx.x * 32 + tx;
    int bidx = gp >> 12;
    int p = gp & (HW - 1);
    size_t base = (size_t)bidx * CDIM * HW + p;

    float vals[32];
    float s = 0.f, s2 = 0.f;
#pragma unroll
    for (int i = 0; i < 32; i++) {
        int c = ty + i * 8;
        float v = x[base + (size_t)c * HW];
        vals[i] = v; s += v; s2 += v * v;
    }
    __shared__ float rs[8][32], rs2[8][32];
    rs[ty][tx] = s; rs2[ty][tx] = s2;
    __syncthreads();
    for (int st = 4; st > 0; st >>= 1) {
        if (ty < st) { rs[ty][tx] += rs[ty + st][tx]; rs2[ty][tx] += rs2[ty + st][tx]; }
        __syncthreads();
    }
    float mean = rs[0][tx] * (1.0f / CDIM);
    float var  = rs2[0][tx] * (1.0f / CDIM) - mean * mean;
    float inv  = rsqrtf(var + 1e-5f);
#pragma unroll
    for (int i = 0; i < 32; i++) {
        int c = ty + i * 8;
        out[base + (size_t)c * HW] = tf32r((vals[i] - mean) * inv * gw[c] + bw[c]);
    }
}

// ---------------- final: LN(g_y) * gamma + query_source -> d_out -----------
__global__ void final_kernel(const float* __restrict__ qsrc,
                             const float* __restrict__ gw,
                             const float* __restrict__ bw,
                             const float* __restrict__ gamma,
                             float* __restrict__ out) {
    int tx = threadIdx.x, ty = threadIdx.y;
    int gp = blockIdx.x * 32 + tx;
    int bidx = gp >> 12;
    int p = gp & (HW - 1);
    size_t base = (size_t)bidx * CDIM * HW + p;

    float vals[32];
    float s = 0.f, s2 = 0.f;
#pragma unroll
    for (int i = 0; i < 32; i++) {
        int c = ty + i * 8;
        float v = g_y[base + (size_t)c * HW];
        vals[i] = v; s += v; s2 += v * v;
    }
    __shared__ float rs[8][32], rs2[8][32];
    rs[ty][tx] = s; rs2[ty][tx] = s2;
    __syncthreads();
    for (int st = 4; st > 0; st >>= 1) {
        if (ty < st) { rs[ty][tx] += rs[ty + st][tx]; rs2[ty][tx] += rs2[ty + st][tx]; }
        __syncthreads();
    }
    float mean = rs[0][tx] * (1.0f / CDIM);
    float var  = rs2[0][tx] * (1.0f / CDIM) - mean * mean;
    float inv  = rsqrtf(var + 1e-5f);
    float gm = gamma[0];
#pragma unroll
    for (int i = 0; i < 32; i++) {
        int c = ty + i * 8;
        float ln = (vals[i] - mean) * inv * gw[c] + bw[c];
        out[base + (size_t)c * HW] = gm * ln + qsrc[base + (size_t)c * HW];
    }
}

// ---------------- cp.async helpers -----------------------------------------
__device__ __forceinline__ void cpasync16(uint32_t smem, const void* g) {
    asm volatile("cp.async.cg.shared.global [%0], [%1], 16;\n" :: "r"(smem), "l"(g));
}
#define CP_COMMIT() asm volatile("cp.async.commit_group;\n" ::: "memory")
#define CP_WAIT0()  asm volatile("cp.async.wait_group 0;\n" ::: "memory")

// ---------------- tensor-core batched GEMM (tf32 mma.sync) -----------------
// C[b](MxN) = A(MxK) * X[b](KxN), N=4096.  128x128 tile, BK=16, 2-stage
// cp.async pipeline, 8 warps (2x4), warp tile 64x32, m16n8k8 fragments.
#define AS_STRIDE 20    // 16 + 4 pad (80B rows, 16B aligned)
#define BS_STRIDE 132   // 128 + 4 pad (528B rows, 16B aligned)

__global__ void __launch_bounds__(256)
tgemm_kernel(const float* __restrict__ A, int M, int K, int sel) {
    const float* Bp; float* Cp;
    if (sel == 0)      { Bp = g_ctx; Cp = g_kv; }
    else if (sel == 1) { Bp = g_qs;  Cp = g_q;  }
    else               { Bp = g_att; Cp = g_y;  }
    Bp += (size_t)blockIdx.z * K * HW;
    Cp += (size_t)blockIdx.z * M * HW;

    __shared__ __align__(16) float As[2][128][AS_STRIDE];  // [m][k]
    __shared__ __align__(16) float Bs[2][16][BS_STRIDE];   // [k][n]

    int m0 = blockIdx.y * 128, n0 = blockIdx.x * 128;
    int tid = threadIdx.x;
    int wid = tid >> 5, lane = tid & 31;
    int wm = wid >> 2, wn = wid & 3;          // warp 2x4
    int gid = lane >> 2, tq = lane & 3;

    // gmem->smem mapping: 2 float4 per thread per tile
    int am = tid >> 1;                 // A row (0..127)
    int ak = (tid & 1) * 8;            // A k-offset (0 or 8), 2 float4 each
    int bk = tid >> 4;                 // B k-row (0..15)
    int bn = (tid & 15) * 8;           // B n-offset, 2 float4 each

    auto load_stage = [&](int s, int k0) {
        uint32_t adst = (uint32_t)__cvta_generic_to_shared(&As[s][am][ak]);
        const float* asrc = A + (size_t)(m0 + am) * K + k0 + ak;
        cpasync16(adst, asrc);
        cpasync16(adst + 16, asrc + 4);
        uint32_t bdst = (uint32_t)__cvta_generic_to_shared(&Bs[s][bk][bn]);
        const float* bsrc = Bp + (size_t)(k0 + bk) * HW + n0 + bn;
        cpasync16(bdst, bsrc);
        cpasync16(bdst + 16, bsrc + 4);
    };

    float acc[4][4][4];
#pragma unroll
    for (int i = 0; i < 4; i++)
#pragma unroll
        for (int j = 0; j < 4; j++)
#pragma unroll
            for (int r = 0; r < 4; r++) acc[i][j][r] = 0.f;

    int KT = K >> 4;
    load_stage(0, 0);
    CP_COMMIT();

    for (int kt = 0; kt < KT; kt++) {
        CP_WAIT0();
        __syncthreads();
        if (kt + 1 < KT) { load_stage((kt + 1) & 1, (kt + 1) << 4); CP_COMMIT(); }
        int buf = kt & 1;

#pragma unroll
        for (int ks = 0; ks < 2; ks++) {
            int kk = ks * 8 + tq;
            uint32_t af[4][4], bf[4][2];
#pragma unroll
            for (int i = 0; i < 4; i++) {
                int r = wm * 64 + i * 16 + gid;
                af[i][0] = tf32u(As[buf][r][kk]);
                af[i][1] = tf32u(As[buf][r + 8][kk]);
                af[i][2] = tf32u(As[buf][r][kk + 4]);
                af[i][3] = tf32u(As[buf][r + 8][kk + 4]);
            }
#pragma unroll
            for (int j = 0; j < 4; j++) {
                int c = wn * 32 + j * 8 + gid;
                bf[j][0] = __float_as_uint(Bs[buf][kk][c]);       // activations pre-rounded
                bf[j][1] = __float_as_uint(Bs[buf][kk + 4][c]);
            }
#pragma unroll
            for (int i = 0; i < 4; i++)
#pragma unroll
                for (int j = 0; j < 4; j++) {
                    asm volatile(
                        "mma.sync.aligned.m16n8k8.row.col.f32.tf32.tf32.f32 "
                        "{%0,%1,%2,%3}, {%4,%5,%6,%7}, {%8,%9}, {%0,%1,%2,%3};"
                        : "+f"(acc[i][j][0]), "+f"(acc[i][j][1]),
                          "+f"(acc[i][j][2]), "+f"(acc[i][j][3])
                        : "r"(af[i][0]), "r"(af[i][1]), "r"(af[i][2]), "r"(af[i][3]),
                          "r"(bf[j][0]), "r"(bf[j][1]));
                }
        }
        __syncthreads();
    }

    // epilogue
#pragma unroll
    for (int i = 0; i < 4; i++) {
        int r = m0 + wm * 64 + i * 16 + gid;
#pragma unroll
        for (int j = 0; j < 4; j++) {
            int c = n0 + wn * 32 + j * 8 + 2 * tq;
            *(float2*)(Cp + (size_t)r * HW + c)       = make_float2(acc[i][j][0], acc[i][j][1]);
            *(float2*)(Cp + (size_t)(r + 8) * HW + c) = make_float2(acc[i][j][2], acc[i][j][3]);
        }
    }
}

// ---------------- l2norm q (in place) + q_probe accumulation ---------------
__global__ void l2q_kernel() {
    int tx = threadIdx.x, ty = threadIdx.y;
    int bh = blockIdx.x >> 7;
    int pix = (blockIdx.x & 127) * 32 + tx;
    size_t base = (size_t)bh * 64 * HW + pix;

    float v[8]; float s = 0.f;
#pragma unroll
    for (int i = 0; i < 8; i++) {
        int d = ty + i * 8;
        v[i] = g_q[base + (size_t)d * HW];
        s += v[i] * v[i];
    }
    __shared__ float rs[8][32];
    rs[ty][tx] = s; __syncthreads();
    for (int st = 4; st > 0; st >>= 1) { if (ty < st) rs[ty][tx] += rs[ty + st][tx]; __syncthreads(); }
    float n = sqrtf(rs[0][tx]);
    float inv = 1.0f / fmaxf(n, 1e-12f);
#pragma unroll
    for (int i = 0; i < 8; i++) {
        int d = ty + i * 8;
        float qn = v[i] * inv;
        g_q[base + (size_t)d * HW] = qn;
        float r = qn;
#pragma unroll
        for (int o = 16; o > 0; o >>= 1) r += __shfl_down_sync(0xffffffffu, r, o);
        if (tx == 0) atomicAdd(&g_qprobe[bh * 64 + d], r);
    }
}

// ---------------- l2norm k (in place) + row/col |k| sums -------------------
__global__ void l2k_kernel() {
    int tx = threadIdx.x, ty = threadIdx.y;
    int bh = blockIdx.x >> 7;
    int pixb = (blockIdx.x & 127) * 32;
    int pix = pixb + tx;
    int b = bh >> 3, head = bh & 7;
    size_t cbase = (size_t)(b * 16 + head) * 64 * HW;
    int h = pix >> 6, w = pix & 63;

    float v[8]; float s = 0.f;
#pragma unroll
    for (int i = 0; i < 8; i++) {
        int d = ty + i * 8;
        v[i] = g_kv[cbase + (size_t)d * HW + pix];
        s += v[i] * v[i];
    }
    __shared__ float rs[8][32];
    rs[ty][tx] = s; __syncthreads();
    for (int st = 4; st > 0; st >>= 1) { if (ty < st) rs[ty][tx] += rs[ty + st][tx]; __syncthreads(); }
    float n = sqrtf(rs[0][tx]);
    float inv = 1.0f / fmaxf(n, 1e-12f);
#pragma unroll
    for (int i = 0; i < 8; i++) {
        int d = ty + i * 8;
        float kn = v[i] * inv;
        g_kv[cbase + (size_t)d * HW + pix] = kn;
        float a = fabsf(kn);
        float r = a;
#pragma unroll
        for (int o = 16; o > 0; o >>= 1) r += __shfl_down_sync(0xffffffffu, r, o);
        if (tx == 0) atomicAdd(&g_rowabs[bh * 4096 + d * 64 + h], r);
        atomicAdd(&g_colabs[bh * 4096 + d * 64 + w], a);
    }
}

// ---------------- scores + top-8 selection ---------------------------------
__global__ void score_kernel() {
    int bh = blockIdx.x;
    int t = threadIdx.x;
    __shared__ float qp[64], sc[64];
    qp[t] = g_qprobe[bh * 64 + t];
    __syncthreads();

    float s = 0.f;
    for (int d = 0; d < 64; d++) s += qp[d] * g_rowabs[bh * 4096 + d * 64 + t];
    sc[t] = s;
    __syncthreads();
    if (t == 0) {
        for (int it = 0; it < 8; it++) {
            int best = 0; float bv = sc[0];
            for (int h = 1; h < 64; h++) if (sc[h] > bv) { bv = sc[h]; best = h; }
            g_idxh[bh * 8 + it] = best; sc[best] = -3e38f;
        }
    }
    __syncthreads();

    float s2 = 0.f;
    for (int d = 0; d < 64; d++) s2 += qp[d] * g_colabs[bh * 4096 + d * 64 + t];
    sc[t] = s2;
    __syncthreads();
    if (t == 0) {
        for (int it = 0; it < 8; it++) {
            int best = 0; float bv = sc[0];
            for (int w = 1; w < 64; w++) if (sc[w] > bv) { bv = sc[w]; best = w; }
            g_idxw[bh * 8 + it] = best; sc[best] = -3e38f;
        }
    }
}

// ---------------- gather selected K/V into dense [bh][64][64] --------------
__global__ void gather_kernel() {
    int bh = blockIdx.x;
    int b = bh >> 3, head = bh & 7;
    size_t kc = (size_t)(b * 16 + head) * 64 * HW;
    size_t vc = (size_t)(b * 16 + 8 + head) * 64 * HW;
    __shared__ int ih[8], iw[8];
    if (threadIdx.x < 8) ih[threadIdx.x] = g_idxh[bh * 8 + threadIdx.x];
    else if (threadIdx.x < 16) iw[threadIdx.x - 8] = g_idxw[bh * 8 + threadIdx.x - 8];
    __syncthreads();
    for (int t = threadIdx.x; t < 4096; t += 256) {
        int j = t >> 6, d = t & 63;
        int r = j >> 3, c = j & 7;
        int pix = ih[r] * 64 + iw[c];
        g_ksel[bh * 4096 + t] = g_kv[kc + (size_t)d * HW + pix];
        g_vsel[bh * 4096 + t] = g_kv[vc + (size_t)d * HW + pix];
    }
}

// ---------------- attention: 4096 queries x 64 kv per head -----------------
__global__ void __launch_bounds__(128)
attn_kernel() {
    __shared__ float ks[64 * 64];
    __shared__ float vs[64 * 64];
    int bh = blockIdx.y;
    int pix = blockIdx.x * 128 + threadIdx.x;

    const float4* kg = (const float4*)&g_ksel[bh * 4096];
    const float4* vg = (const float4*)&g_vsel[bh * 4096];
    float4* ks4 = (float4*)ks; float4* vs4 = (float4*)vs;
    for (int i = threadIdx.x; i < 1024; i += 128) { ks4[i] = kg[i]; vs4[i] = vg[i]; }
    __syncthreads();

    size_t qb = (size_t)bh * 64 * HW + pix;
    float sim[64];
#pragma unroll
    for (int j = 0; j < 64; j++) sim[j] = 0.f;

    for (int dc = 0; dc < 64; dc += 16) {
        float q0[16];
#pragma unroll
        for (int i = 0; i < 16; i++) q0[i] = g_q[qb + (size_t)(dc + i) * HW];
#pragma unroll
        for (int j = 0; j < 64; j++) {
            const float4* kr = (const float4*)&ks[j * 64 + dc];
#pragma unroll
            for (int i4 = 0; i4 < 4; i4++) {
                float4 kvv = kr[i4];
                sim[j] += q0[i4*4+0]*kvv.x + q0[i4*4+1]*kvv.y
                        + q0[i4*4+2]*kvv.z + q0[i4*4+3]*kvv.w;
            }
        }
    }
    float mx = sim[0];
#pragma unroll
    for (int j = 1; j < 64; j++) mx = fmaxf(mx, sim[j]);
    float sum = 0.f;
#pragma unroll
    for (int j = 0; j < 64; j++) { sim[j] = expf(sim[j] - mx); sum += sim[j]; }
    float invs = 1.0f / sum;

    size_t ob = (size_t)bh * 64 * HW + pix;
    for (int dc = 0; dc < 64; dc += 32) {
        float acc[32];
#pragma unroll
        for (int i = 0; i < 32; i++) acc[i] = 0.f;
#pragma unroll
        for (int j = 0; j < 64; j++) {
            const float4* vr = (const float4*)&vs[j * 64 + dc];
            float p = sim[j];
#pragma unroll
            for (int i4 = 0; i4 < 8; i4++) {
                float4 vv = vr[i4];
                acc[i4*4+0] += p * vv.x; acc[i4*4+1] += p * vv.y;
                acc[i4*4+2] += p * vv.z; acc[i4*4+3] += p * vv.w;
            }
        }
#pragma unroll
        for (int i = 0; i < 32; i++)
            g_att[ob + (size_t)(dc + i) * HW] = tf32r(acc[i] * invs);
    }
}

// ---------------- launch ----------------------------------------------------
extern "C" void kernel_launch(void* const* d_in, const int* in_sizes, int n_in,
                              void* d_out, int out_size) {
    const float* query_source = (const float*)d_in[0];
    const float* context      = (const float*)d_in[1];
    const float* cn_g = (const float*)d_in[2];
    const float* cn_b = (const float*)d_in[3];
    const float* qn_g = (const float*)d_in[4];
    const float* qn_b = (const float*)d_in[5];
    const float* on_g = (const float*)d_in[6];
    const float* on_b = (const float*)d_in[7];
    const float* w_kv  = (const float*)d_in[8];
    const float* w_q   = (const float*)d_in[9];
    const float* w_out = (const float*)d_in[10];
    const float* gamma = (const float*)d_in[11];
    float* out = (float*)d_out;

    dim3 lnb(32, 8);

    zero_kernel<<<1024, 256>>>();
    ln_kernel<<<1024, lnb>>>(context, cn_g, cn_b, 0);
    ln_kernel<<<1024, lnb>>>(query_source, qn_g, qn_b, 1);

    tgemm_kernel<<<dim3(32, 8, 8), 256>>>(w_kv, 1024, 256, 0);
    tgemm_kernel<<<dim3(32, 4, 8), 256>>>(w_q, 512, 256, 1);

    l2q_kernel<<<8192, lnb>>>();
    l2k_kernel<<<8192, lnb>>>();

    score_kernel<<<64, 64>>>();
    gather_kernel<<<64, 256>>>();

    attn_kernel<<<dim3(32, 64), 128>>>();

    tgemm_kernel<<<dim3(32, 2, 8), 256>>>(w_out, 256, 512, 2);

    final_kernel<<<1024, lnb>>>(query_source, on_g, on_b, gamma, out);
}

// round 4
// speedup vs baseline: 1.9377x; 1.0412x over previous
#include <cuda_runtime.h>
#include <math.h>
#include <stdint.h>

#define HW    4096
#define CDIM  256
#define BATCH 8
#define NBH   64     // B*HEADS
#define DH    64     // DIM_HEAD

// ---------------- scratch (device globals; no runtime allocation) ----------
__device__ float g_ctx[BATCH * CDIM * HW];        // layernormed context (tf32-rounded)
__device__ float g_qs [BATCH * CDIM * HW];        // layernormed query_source (tf32-rounded)
__device__ float g_kv [BATCH * 1024 * HW];        // w_kv output (k then v per batch)
__device__ float g_q  [BATCH * 512  * HW];        // w_q output (l2-normalized in place)
__device__ float g_att[BATCH * 512  * HW];        // attention output (tf32-rounded)
__device__ float g_y  [BATCH * CDIM * HW];        // w_out output
__device__ float g_qprobe[NBH * DH];
__device__ float g_rowabs[NBH * DH * 64];         // [bh][d][h]
__device__ float g_colabs[NBH * DH * 64];         // [bh][d][w]
__device__ int   g_idxh[NBH * 8];
__device__ int   g_idxw[NBH * 8];
__device__ float g_ksel[NBH * 64 * DH];           // [bh][j][d]
__device__ float g_vsel[NBH * 64 * DH];

// tf32-pre-rounded weights
__device__ float g_wkvp[1024 * 256];
__device__ float g_wqp [512 * 256];
__device__ float g_woutp[256 * 512];

__device__ __forceinline__ float tf32r(float x) {
    uint32_t u;
    asm("cvt.rna.tf32.f32 %0, %1;" : "=r"(u) : "f"(x));
    return __uint_as_float(u);
}

// ---------------- zero scratch reductions ----------------------------------
__global__ void zero_kernel() {
    int i = blockIdx.x * 256 + threadIdx.x;
    if (i < NBH * DH) g_qprobe[i] = 0.f;
    if (i < NBH * DH * 64) { g_rowabs[i] = 0.f; g_colabs[i] = 0.f; }
}

// ---------------- weight prep: round to tf32 (no fold) ---------------------
// 2048 blocks x 256 threads, flat over 524288 weight elements.
__global__ void prep_w(const float* __restrict__ wkv,
                       const float* __restrict__ wq,
                       const float* __restrict__ wout) {
    int i = blockIdx.x * 256 + threadIdx.x;
    if (i < 262144) g_wkvp[i] = tf32r(wkv[i]);
    else if (i < 393216) g_wqp[i - 262144] = tf32r(wq[i - 262144]);
    else g_woutp[i - 393216] = tf32r(wout[i - 393216]);
}

// ---------------- channel layernorm (per pixel over 256 channels) ----------
__global__ void ln_kernel(const float* __restrict__ x,
                          const float* __restrict__ gw,
                          const float* __restrict__ bw,
                          int outsel) {
    float* out = outsel ? g_qs : g_ctx;
    int tx = threadIdx.x, ty = threadIdx.y;
    int gp = blockIdx.x * 32 + tx;
    int bidx = gp >> 12;
    int p = gp & (HW - 1);
    size_t base = (size_t)bidx * CDIM * HW + p;

    float vals[32];
    float s = 0.f, s2 = 0.f;
#pragma unroll
    for (int i = 0; i < 32; i++) {
        int c = ty + i * 8;
        float v = x[base + (size_t)c * HW];
        vals[i] = v; s += v; s2 += v * v;
    }
    __shared__ float rs[8][32], rs2[8][32];
    rs[ty][tx] = s; rs2[ty][tx] = s2;
    __syncthreads();
    for (int st = 4; st > 0; st >>= 1) {
        if (ty < st) { rs[ty][tx] += rs[ty + st][tx]; rs2[ty][tx] += rs2[ty + st][tx]; }
        __syncthreads();
    }
    float mean = rs[0][tx] * (1.0f / CDIM);
    float var  = rs2[0][tx] * (1.0f / CDIM) - mean * mean;
    float inv  = rsqrtf(var + 1e-5f);
#pragma unroll
    for (int i = 0; i < 32; i++) {
        int c = ty + i * 8;
        out[base + (size_t)c * HW] = tf32r((vals[i] - mean) * inv * gw[c] + bw[c]);
    }
}

// ---------------- final: LN(g_y) * gamma + query_source -> d_out -----------
__global__ void final_kernel(const float* __restrict__ qsrc,
                             const float* __restrict__ gw,
                             const float* __restrict__ bw,
                             const float* __restrict__ gamma,
                             float* __restrict__ out) {
    int tx = threadIdx.x, ty = threadIdx.y;
    int gp = blockIdx.x * 32 + tx;
    int bidx = gp >> 12;
    int p = gp & (HW - 1);
    size_t base = (size_t)bidx * CDIM * HW + p;

    float vals[32];
    float s = 0.f, s2 = 0.f;
#pragma unroll
    for (int i = 0; i < 32; i++) {
        int c = ty + i * 8;
        float v = g_y[base + (size_t)c * HW];
        vals[i] = v; s += v; s2 += v * v;
    }
    __shared__ float rs[8][32], rs2[8][32];
    rs[ty][tx] = s; rs2[ty][tx] = s2;
    __syncthreads();
    for (int st = 4; st > 0; st >>= 1) {
        if (ty < st) { rs[ty][tx] += rs[ty + st][tx]; rs2[ty][tx] += rs2[ty + st][tx]; }
        __syncthreads();
    }
    float mean = rs[0][tx] * (1.0f / CDIM);
    float var  = rs2[0][tx] * (1.0f / CDIM) - mean * mean;
    float inv  = rsqrtf(var + 1e-5f);
    float gm = gamma[0];
#pragma unroll
    for (int i = 0; i < 32; i++) {
        int c = ty + i * 8;
        float ln = (vals[i] - mean) * inv * gw[c] + bw[c];
        out[base + (size_t)c * HW] = gm * ln + qsrc[base + (size_t)c * HW];
    }
}

// ---------------- cp.async helpers -----------------------------------------
__device__ __forceinline__ void cpasync16(uint32_t smem, const void* g) {
    asm volatile("cp.async.cg.shared.global [%0], [%1], 16;\n" :: "r"(smem), "l"(g));
}
#define CP_COMMIT() asm volatile("cp.async.commit_group;\n" ::: "memory")
#define CP_WAIT0()  asm volatile("cp.async.wait_group 0;\n" ::: "memory")

// ---------------- tensor-core batched GEMM (tf32 mma.sync) -----------------
// C[b](MxN) = A(MxK) * X[b](KxN), N=4096.  128x128 tile, BK=16, 2-stage
// cp.async pipeline, 8 warps (2x4), warp tile 64x32, m16n8k8 fragments.
// Both operands pre-rounded to tf32 -> zero cvt in mainloop.
#define AS_STRIDE 20    // 16 + 4 pad
#define BS_STRIDE 136   // 128 + 8 pad (conflict-free fragment loads)

__global__ void __launch_bounds__(256)
tgemm_kernel(int M, int K, int sel) {
    const float* Ap; const float* Bp; float* Cp;
    if (sel == 0)      { Ap = g_wkvp;  Bp = g_ctx; Cp = g_kv; }
    else if (sel == 1) { Ap = g_wqp;   Bp = g_qs;  Cp = g_q;  }
    else               { Ap = g_woutp; Bp = g_att; Cp = g_y;  }
    Bp += (size_t)blockIdx.z * K * HW;
    Cp += (size_t)blockIdx.z * M * HW;

    __shared__ __align__(16) float As[2][128][AS_STRIDE];  // [m][k]
    __shared__ __align__(16) float Bs[2][16][BS_STRIDE];   // [k][n]

    int m0 = blockIdx.y * 128, n0 = blockIdx.x * 128;
    int tid = threadIdx.x;
    int wid = tid >> 5, lane = tid & 31;
    int wm = wid >> 2, wn = wid & 3;          // warp 2x4
    int gid = lane >> 2, tq = lane & 3;

    int am = tid >> 1;
    int ak = (tid & 1) * 8;
    int bk = tid >> 4;
    int bn = (tid & 15) * 8;

    auto load_stage = [&](int s, int k0) {
        uint32_t adst = (uint32_t)__cvta_generic_to_shared(&As[s][am][ak]);
        const float* asrc = Ap + (size_t)(m0 + am) * K + k0 + ak;
        cpasync16(adst, asrc);
        cpasync16(adst + 16, asrc + 4);
        uint32_t bdst = (uint32_t)__cvta_generic_to_shared(&Bs[s][bk][bn]);
        const float* bsrc = Bp + (size_t)(k0 + bk) * HW + n0 + bn;
        cpasync16(bdst, bsrc);
        cpasync16(bdst + 16, bsrc + 4);
    };

    float acc[4][4][4];
#pragma unroll
    for (int i = 0; i < 4; i++)
#pragma unroll
        for (int j = 0; j < 4; j++)
#pragma unroll
            for (int r = 0; r < 4; r++) acc[i][j][r] = 0.f;

    int KT = K >> 4;
    load_stage(0, 0);
    CP_COMMIT();

    for (int kt = 0; kt < KT; kt++) {
        CP_WAIT0();
        __syncthreads();
        if (kt + 1 < KT) { load_stage((kt + 1) & 1, (kt + 1) << 4); CP_COMMIT(); }
        int buf = kt & 1;

#pragma unroll
        for (int ks = 0; ks < 2; ks++) {
            int kk = ks * 8 + tq;
            uint32_t af[4][4], bf[4][2];
#pragma unroll
            for (int i = 0; i < 4; i++) {
                int r = wm * 64 + i * 16 + gid;
                af[i][0] = __float_as_uint(As[buf][r][kk]);
                af[i][1] = __float_as_uint(As[buf][r + 8][kk]);
                af[i][2] = __float_as_uint(As[buf][r][kk + 4]);
                af[i][3] = __float_as_uint(As[buf][r + 8][kk + 4]);
            }
#pragma unroll
            for (int j = 0; j < 4; j++) {
                int c = wn * 32 + j * 8 + gid;
                bf[j][0] = __float_as_uint(Bs[buf][kk][c]);
                bf[j][1] = __float_as_uint(Bs[buf][kk + 4][c]);
            }
#pragma unroll
            for (int i = 0; i < 4; i++)
#pragma unroll
                for (int j = 0; j < 4; j++) {
                    asm volatile(
                        "mma.sync.aligned.m16n8k8.row.col.f32.tf32.tf32.f32 "
                        "{%0,%1,%2,%3}, {%4,%5,%6,%7}, {%8,%9}, {%0,%1,%2,%3};"
                        : "+f"(acc[i][j][0]), "+f"(acc[i][j][1]),
                          "+f"(acc[i][j][2]), "+f"(acc[i][j][3])
                        : "r"(af[i][0]), "r"(af[i][1]), "r"(af[i][2]), "r"(af[i][3]),
                          "r"(bf[j][0]), "r"(bf[j][1]));
                }
        }
        __syncthreads();
    }

    // epilogue
#pragma unroll
    for (int i = 0; i < 4; i++) {
        int r = m0 + wm * 64 + i * 16 + gid;
#pragma unroll
        for (int j = 0; j < 4; j++) {
            int c = n0 + wn * 32 + j * 8 + 2 * tq;
            *(float2*)(Cp + (size_t)r * HW + c)       = make_float2(acc[i][j][0], acc[i][j][1]);
            *(float2*)(Cp + (size_t)(r + 8) * HW + c) = make_float2(acc[i][j][2], acc[i][j][3]);
        }
    }
}

// ---------------- l2norm q (in place) + q_probe accumulation ---------------
__global__ void l2q_kernel() {
    int tx = threadIdx.x, ty = threadIdx.y;
    int bh = blockIdx.x >> 7;
    int pix = (blockIdx.x & 127) * 32 + tx;
    size_t base = (size_t)bh * 64 * HW + pix;

    float v[8]; float s = 0.f;
#pragma unroll
    for (int i = 0; i < 8; i++) {
        int d = ty + i * 8;
        v[i] = g_q[base + (size_t)d * HW];
        s += v[i] * v[i];
    }
    __shared__ float rs[8][32];
    rs[ty][tx] = s; __syncthreads();
    for (int st = 4; st > 0; st >>= 1) { if (ty < st) rs[ty][tx] += rs[ty + st][tx]; __syncthreads(); }
    float n = sqrtf(rs[0][tx]);
    float inv = 1.0f / fmaxf(n, 1e-12f);
#pragma unroll
    for (int i = 0; i < 8; i++) {
        int d = ty + i * 8;
        float qn = v[i] * inv;
        g_q[base + (size_t)d * HW] = qn;
        float r = qn;
#pragma unroll
        for (int o = 16; o > 0; o >>= 1) r += __shfl_down_sync(0xffffffffu, r, o);
        if (tx == 0) atomicAdd(&g_qprobe[bh * 64 + d], r);
    }
}

// ---------------- l2norm k (in place) + row/col |k| sums -------------------
__global__ void l2k_kernel() {
    int tx = threadIdx.x, ty = threadIdx.y;
    int bh = blockIdx.x >> 7;
    int pixb = (blockIdx.x & 127) * 32;
    int pix = pixb + tx;
    int b = bh >> 3, head = bh & 7;
    size_t cbase = (size_t)(b * 16 + head) * 64 * HW;
    int h = pix >> 6, w = pix & 63;

    float v[8]; float s = 0.f;
#pragma unroll
    for (int i = 0; i < 8; i++) {
        int d = ty + i * 8;
        v[i] = g_kv[cbase + (size_t)d * HW + pix];
        s += v[i] * v[i];
    }
    __shared__ float rs[8][32];
    rs[ty][tx] = s; __syncthreads();
    for (int st = 4; st > 0; st >>= 1) { if (ty < st) rs[ty][tx] += rs[ty + st][tx]; __syncthreads(); }
    float n = sqrtf(rs[0][tx]);
    float inv = 1.0f / fmaxf(n, 1e-12f);
#pragma unroll
    for (int i = 0; i < 8; i++) {
        int d = ty + i * 8;
        float kn = v[i] * inv;
        g_kv[cbase + (size_t)d * HW + pix] = kn;
        float a = fabsf(kn);
        float r = a;
#pragma unroll
        for (int o = 16; o > 0; o >>= 1) r += __shfl_down_sync(0xffffffffu, r, o);
        if (tx == 0) atomicAdd(&g_rowabs[bh * 4096 + d * 64 + h], r);
        atomicAdd(&g_colabs[bh * 4096 + d * 64 + w], a);
    }
}

// ---------------- scores + top-8 selection ---------------------------------
__global__ void score_kernel() {
    int bh = blockIdx.x;
    int t = threadIdx.x;
    __shared__ float qp[64], sc[64];
    qp[t] = g_qprobe[bh * 64 + t];
    __syncthreads();

    float s = 0.f;
    for (int d = 0; d < 64; d++) s += qp[d] * g_rowabs[bh * 4096 + d * 64 + t];
    sc[t] = s;
    __syncthreads();
    if (t == 0) {
        for (int it = 0; it < 8; it++) {
            int best = 0; float bv = sc[0];
            for (int h = 1; h < 64; h++) if (sc[h] > bv) { bv = sc[h]; best = h; }
            g_idxh[bh * 8 + it] = best; sc[best] = -3e38f;
        }
    }
    __syncthreads();

    float s2 = 0.f;
    for (int d = 0; d < 64; d++) s2 += qp[d] * g_colabs[bh * 4096 + d * 64 + t];
    sc[t] = s2;
    __syncthreads();
    if (t == 0) {
        for (int it = 0; it < 8; it++) {
            int best = 0; float bv = sc[0];
            for (int w = 1; w < 64; w++) if (sc[w] > bv) { bv = sc[w]; best = w; }
            g_idxw[bh * 8 + it] = best; sc[best] = -3e38f;
        }
    }
}

// ---------------- gather selected K/V into dense [bh][64][64] --------------
__global__ void gather_kernel() {
    int bh = blockIdx.x;
    int b = bh >> 3, head = bh & 7;
    size_t kc = (size_t)(b * 16 + head) * 64 * HW;
    size_t vc = (size_t)(b * 16 + 8 + head) * 64 * HW;
    __shared__ int ih[8], iw[8];
    if (threadIdx.x < 8) ih[threadIdx.x] = g_idxh[bh * 8 + threadIdx.x];
    else if (threadIdx.x < 16) iw[threadIdx.x - 8] = g_idxw[bh * 8 + threadIdx.x - 8];
    __syncthreads();
    for (int t = threadIdx.x; t < 4096; t += 256) {
        int j = t >> 6, d = t & 63;
        int r = j >> 3, c = j & 7;
        int pix = ih[r] * 64 + iw[c];
        g_ksel[bh * 4096 + t] = g_kv[kc + (size_t)d * HW + pix];
        g_vsel[bh * 4096 + t] = g_kv[vc + (size_t)d * HW + pix];
    }
}

// ---------------- attention: 4096 queries x 64 kv per head -----------------
__global__ void __launch_bounds__(128)
attn_kernel() {
    __shared__ float ks[64 * 64];
    __shared__ float vs[64 * 64];
    int bh = blockIdx.y;
    int pix = blockIdx.x * 128 + threadIdx.x;

    const float4* kg = (const float4*)&g_ksel[bh * 4096];
    const float4* vg = (const float4*)&g_vsel[bh * 4096];
    float4* ks4 = (float4*)ks; float4* vs4 = (float4*)vs;
    for (int i = threadIdx.x; i < 1024; i += 128) { ks4[i] = kg[i]; vs4[i] = vg[i]; }
    __syncthreads();

    size_t qb = (size_t)bh * 64 * HW + pix;
    float sim[64];
#pragma unroll
    for (int j = 0; j < 64; j++) sim[j] = 0.f;

    for (int dc = 0; dc < 64; dc += 16) {
        float q0[16];
#pragma unroll
        for (int i = 0; i < 16; i++) q0[i] = g_q[qb + (size_t)(dc + i) * HW];
#pragma unroll
        for (int j = 0; j < 64; j++) {
            const float4* kr = (const float4*)&ks[j * 64 + dc];
#pragma unroll
            for (int i4 = 0; i4 < 4; i4++) {
                float4 kvv = kr[i4];
                sim[j] += q0[i4*4+0]*kvv.x + q0[i4*4+1]*kvv.y
                        + q0[i4*4+2]*kvv.z + q0[i4*4+3]*kvv.w;
            }
        }
    }
    float mx = sim[0];
#pragma unroll
    for (int j = 1; j < 64; j++) mx = fmaxf(mx, sim[j]);
    float sum = 0.f;
#pragma unroll
    for (int j = 0; j < 64; j++) { sim[j] = expf(sim[j] - mx); sum += sim[j]; }
    float invs = 1.0f / sum;

    size_t ob = (size_t)bh * 64 * HW + pix;
    for (int dc = 0; dc < 64; dc += 32) {
        float acc[32];
#pragma unroll
        for (int i = 0; i < 32; i++) acc[i] = 0.f;
#pragma unroll
        for (int j = 0; j < 64; j++) {
            const float4* vr = (const float4*)&vs[j * 64 + dc];
            float p = sim[j];
#pragma unroll
            for (int i4 = 0; i4 < 8; i4++) {
                float4 vv = vr[i4];
                acc[i4*4+0] += p * vv.x; acc[i4*4+1] += p * vv.y;
                acc[i4*4+2] += p * vv.z; acc[i4*4+3] += p * vv.w;
            }
        }
#pragma unroll
        for (int i = 0; i < 32; i++)
            g_att[ob + (size_t)(dc + i) * HW] = tf32r(acc[i] * invs);
    }
}

// ---------------- launch ----------------------------------------------------
extern "C" void kernel_launch(void* const* d_in, const int* in_sizes, int n_in,
                              void* d_out, int out_size) {
    const float* query_source = (const float*)d_in[0];
    const float* context      = (const float*)d_in[1];
    const float* cn_g = (const float*)d_in[2];
    const float* cn_b = (const float*)d_in[3];
    const float* qn_g = (const float*)d_in[4];
    const float* qn_b = (const float*)d_in[5];
    const float* on_g = (const float*)d_in[6];
    const float* on_b = (const float*)d_in[7];
    const float* w_kv  = (const float*)d_in[8];
    const float* w_q   = (const float*)d_in[9];
    const float* w_out = (const float*)d_in[10];
    const float* gamma = (const float*)d_in[11];
    float* out = (float*)d_out;

    dim3 lnb(32, 8);

    zero_kernel<<<1024, 256>>>();
    prep_w<<<2048, 256>>>(w_kv, w_q, w_out);
    ln_kernel<<<1024, lnb>>>(context, cn_g, cn_b, 0);
    ln_kernel<<<1024, lnb>>>(query_source, qn_g, qn_b, 1);

    tgemm_kernel<<<dim3(32, 8, 8), 256>>>(1024, 256, 0);
    tgemm_kernel<<<dim3(32, 4, 8), 256>>>(512, 256, 1);

    l2q_kernel<<<8192, lnb>>>();
    l2k_kernel<<<8192, lnb>>>();

    score_kernel<<<64, 64>>>();
    gather_kernel<<<64, 256>>>();

    attn_kernel<<<dim3(32, 64), 128>>>();

    tgemm_kernel<<<dim3(32, 2, 8), 256>>>(256, 512, 2);

    final_kernel<<<1024, lnb>>>(query_source, on_g, on_b, gamma, out);
}

// round 5
// speedup vs baseline: 2.2249x; 1.1482x over previous
#include <cuda_runtime.h>
#include <math.h>
#include <stdint.h>

#define HW    4096
#define CDIM  256
#define BATCH 8
#define NBH   64     // B*HEADS
#define DH    64     // DIM_HEAD

// ---------------- scratch (device globals; no runtime allocation) ----------
__device__ float g_ctx[BATCH * CDIM * HW];        // layernormed context (tf32-rounded)
__device__ float g_qs [BATCH * CDIM * HW];        // layernormed query_source (tf32-rounded)
__device__ float g_kv [BATCH * 1024 * HW];        // w_kv output (k then v per batch)
__device__ float g_q  [BATCH * 512  * HW];        // w_q output (l2-normalized in place)
__device__ float g_att[BATCH * 512  * HW];        // attention output (tf32-rounded)
__device__ float g_y  [BATCH * CDIM * HW];        // w_out output
__device__ float g_qprobe[NBH * DH];
__device__ float g_rowabs[NBH * DH * 64];         // [bh][d][h]
__device__ float g_colabs[NBH * DH * 64];         // [bh][d][w]
__device__ int   g_idxh[NBH * 8];
__device__ int   g_idxw[NBH * 8];
__device__ float g_ksel[NBH * 64 * DH];           // [bh][j][d]
__device__ float g_vsel[NBH * 64 * DH];

// tf32-pre-rounded weights, packed in mma-fragment order:
// [mtile128][kt16][mblk16][ks8][lane32] -> float4 {A[m][k],A[m+8][k],A[m][k+4],A[m+8][k+4]}
__device__ float g_wkvp[1024 * 256];
__device__ float g_wqp [512 * 256];
__device__ float g_woutp[256 * 512];

__device__ __forceinline__ float tf32r(float x) {
    uint32_t u;
    asm("cvt.rna.tf32.f32 %0, %1;" : "=r"(u) : "f"(x));
    return __uint_as_float(u);
}

// ---------------- zero scratch reductions ----------------------------------
__global__ void zero_kernel() {
    int i = blockIdx.x * 256 + threadIdx.x;
    if (i < NBH * DH) g_qprobe[i] = 0.f;
    if (i < NBH * DH * 64) { g_rowabs[i] = 0.f; g_colabs[i] = 0.f; }
}

// ---------------- weight prep: tf32-round + pack into fragment order -------
// 512 blocks x 256 threads, one float4 per thread (131072 total).
__global__ void prep_w(const float* __restrict__ wkv,
                       const float* __restrict__ wq,
                       const float* __restrict__ wout) {
    int fid = blockIdx.x * 256 + threadIdx.x;
    const float* W; float4* Dst; int K, rel;
    if (fid < 65536)      { W = wkv;  Dst = (float4*)g_wkvp;  K = 256; rel = fid; }
    else if (fid < 98304) { W = wq;   Dst = (float4*)g_wqp;   K = 256; rel = fid - 65536; }
    else                  { W = wout; Dst = (float4*)g_woutp; K = 512; rel = fid - 98304; }
    int KT = K >> 4;
    int per_mtile = KT * 512;
    int mtile = rel / per_mtile;
    int r2 = rel - mtile * per_mtile;
    int kt = r2 >> 9;
    int sub = r2 & 511;
    int mblk = (sub >> 6) & 7;
    int ks = (sub >> 5) & 1;
    int lane = sub & 31;
    int gid = lane >> 2, tq = lane & 3;
    int m = mtile * 128 + mblk * 16 + gid;
    int k = kt * 16 + ks * 8 + tq;
    float4 v;
    v.x = tf32r(W[(size_t)m * K + k]);
    v.y = tf32r(W[(size_t)(m + 8) * K + k]);
    v.z = tf32r(W[(size_t)m * K + k + 4]);
    v.w = tf32r(W[(size_t)(m + 8) * K + k + 4]);
    Dst[rel] = v;
}

// ---------------- channel layernorm (per pixel over 256 channels) ----------
__global__ void ln_kernel(const float* __restrict__ x,
                          const float* __restrict__ gw,
                          const float* __restrict__ bw,
                          int outsel) {
    float* out = outsel ? g_qs : g_ctx;
    int tx = threadIdx.x, ty = threadIdx.y;
    int gp = blockIdx.x * 32 + tx;
    int bidx = gp >> 12;
    int p = gp & (HW - 1);
    size_t base = (size_t)bidx * CDIM * HW + p;

    float vals[32];
    float s = 0.f, s2 = 0.f;
#pragma unroll
    for (int i = 0; i < 32; i++) {
        int c = ty + i * 8;
        float v = x[base + (size_t)c * HW];
        vals[i] = v; s += v; s2 += v * v;
    }
    __shared__ float rs[8][32], rs2[8][32];
    rs[ty][tx] = s; rs2[ty][tx] = s2;
    __syncthreads();
    for (int st = 4; st > 0; st >>= 1) {
        if (ty < st) { rs[ty][tx] += rs[ty + st][tx]; rs2[ty][tx] += rs2[ty + st][tx]; }
        __syncthreads();
    }
    float mean = rs[0][tx] * (1.0f / CDIM);
    float var  = rs2[0][tx] * (1.0f / CDIM) - mean * mean;
    float inv  = rsqrtf(var + 1e-5f);
#pragma unroll
    for (int i = 0; i < 32; i++) {
        int c = ty + i * 8;
        out[base + (size_t)c * HW] = tf32r((vals[i] - mean) * inv * gw[c] + bw[c]);
    }
}

// ---------------- final: LN(g_y) * gamma + query_source -> d_out -----------
__global__ void final_kernel(const float* __restrict__ qsrc,
                             const float* __restrict__ gw,
                             const float* __restrict__ bw,
                             const float* __restrict__ gamma,
                             float* __restrict__ out) {
    int tx = threadIdx.x, ty = threadIdx.y;
    int gp = blockIdx.x * 32 + tx;
    int bidx = gp >> 12;
    int p = gp & (HW - 1);
    size_t base = (size_t)bidx * CDIM * HW + p;

    float vals[32];
    float s = 0.f, s2 = 0.f;
#pragma unroll
    for (int i = 0; i < 32; i++) {
        int c = ty + i * 8;
        float v = g_y[base + (size_t)c * HW];
        vals[i] = v; s += v; s2 += v * v;
    }
    __shared__ float rs[8][32], rs2[8][32];
    rs[ty][tx] = s; rs2[ty][tx] = s2;
    __syncthreads();
    for (int st = 4; st > 0; st >>= 1) {
        if (ty < st) { rs[ty][tx] += rs[ty + st][tx]; rs2[ty][tx] += rs2[ty + st][tx]; }
        __syncthreads();
    }
    float mean = rs[0][tx] * (1.0f / CDIM);
    float var  = rs2[0][tx] * (1.0f / CDIM) - mean * mean;
    float inv  = rsqrtf(var + 1e-5f);
    float gm = gamma[0];
#pragma unroll
    for (int i = 0; i < 32; i++) {
        int c = ty + i * 8;
        float ln = (vals[i] - mean) * inv * gw[c] + bw[c];
        out[base + (size_t)c * HW] = gm * ln + qsrc[base + (size_t)c * HW];
    }
}

// ---------------- cp.async helpers -----------------------------------------
__device__ __forceinline__ void cpasync16(uint32_t smem, const void* g) {
    asm volatile("cp.async.cg.shared.global [%0], [%1], 16;\n" :: "r"(smem), "l"(g));
}
#define CP_COMMIT() asm volatile("cp.async.commit_group;\n" ::: "memory")
#define CP_WAIT1()  asm volatile("cp.async.wait_group 1;\n" ::: "memory")

// ---------------- tensor-core batched GEMM (tf32 mma.sync) -----------------
// C[b](MxN) = A(MxK) * X[b](KxN), N=4096. 128x128 tile, BK=16, 3-stage
// cp.async pipeline, single sync per iteration, 8 warps (2x4), warp 64x32.
// A pre-packed in fragment order -> LDS.128 fragment loads, no padding.
#define BS_STRIDE 136   // 128 + 8 pad (conflict-free B fragment loads)

__global__ void __launch_bounds__(256)
tgemm_kernel(int M, int K, int sel) {
    const uint4* Ap4; const float* Bp; float* Cp;
    if (sel == 0)      { Ap4 = (const uint4*)g_wkvp;  Bp = g_ctx; Cp = g_kv; }
    else if (sel == 1) { Ap4 = (const uint4*)g_wqp;   Bp = g_qs;  Cp = g_q;  }
    else               { Ap4 = (const uint4*)g_woutp; Bp = g_att; Cp = g_y;  }
    int KT = K >> 4;
    Bp += (size_t)blockIdx.z * K * HW;
    Cp += (size_t)blockIdx.z * M * HW;
    Ap4 += (size_t)blockIdx.y * (KT * 512);

    __shared__ __align__(16) uint4 As4[3][512];
    __shared__ __align__(16) float Bs[3][16][BS_STRIDE];

    int m0 = blockIdx.y * 128, n0 = blockIdx.x * 128;
    int tid = threadIdx.x;
    int wid = tid >> 5, lane = tid & 31;
    int wm = wid >> 2, wn = wid & 3;          // warp 2x4
    int gid = lane >> 2, tq = lane & 3;

    int bk = tid >> 4;
    int bn = (tid & 15) * 8;

    auto load_stage = [&](int s, int kt) {
        uint32_t adst = (uint32_t)__cvta_generic_to_shared(&As4[s][tid]);
        const uint4* asrc = Ap4 + kt * 512 + tid;
        cpasync16(adst, asrc);
        adst = (uint32_t)__cvta_generic_to_shared(&As4[s][tid + 256]);
        cpasync16(adst, asrc + 256);
        uint32_t bdst = (uint32_t)__cvta_generic_to_shared(&Bs[s][bk][bn]);
        const float* bsrc = Bp + (size_t)(kt * 16 + bk) * HW + n0 + bn;
        cpasync16(bdst, bsrc);
        cpasync16(bdst + 16, bsrc + 4);
    };

    float acc[4][4][4];
#pragma unroll
    for (int i = 0; i < 4; i++)
#pragma unroll
        for (int j = 0; j < 4; j++)
#pragma unroll
            for (int r = 0; r < 4; r++) acc[i][j][r] = 0.f;

    load_stage(0, 0); CP_COMMIT();
    load_stage(1, 1); CP_COMMIT();

    for (int kt = 0; kt < KT; kt++) {
        CP_WAIT1();
        __syncthreads();
        if (kt + 2 < KT) load_stage((kt + 2) % 3, kt + 2);
        CP_COMMIT();                               // uniform group accounting
        int s = kt % 3;

#pragma unroll
        for (int ks = 0; ks < 2; ks++) {
            int kk = ks * 8 + tq;
            uint4 af[4];
            uint32_t bf[4][2];
#pragma unroll
            for (int i = 0; i < 4; i++)
                af[i] = As4[s][(4 * wm + i) * 64 + ks * 32 + lane];
#pragma unroll
            for (int j = 0; j < 4; j++) {
                int c = wn * 32 + j * 8 + gid;
                bf[j][0] = __float_as_uint(Bs[s][kk][c]);
                bf[j][1] = __float_as_uint(Bs[s][kk + 4][c]);
            }
#pragma unroll
            for (int i = 0; i < 4; i++)
#pragma unroll
                for (int j = 0; j < 4; j++) {
                    asm volatile(
                        "mma.sync.aligned.m16n8k8.row.col.f32.tf32.tf32.f32 "
                        "{%0,%1,%2,%3}, {%4,%5,%6,%7}, {%8,%9}, {%0,%1,%2,%3};"
                        : "+f"(acc[i][j][0]), "+f"(acc[i][j][1]),
                          "+f"(acc[i][j][2]), "+f"(acc[i][j][3])
                        : "r"(af[i].x), "r"(af[i].y), "r"(af[i].z), "r"(af[i].w),
                          "r"(bf[j][0]), "r"(bf[j][1]));
                }
        }
    }

    // epilogue
#pragma unroll
    for (int i = 0; i < 4; i++) {
        int r = m0 + wm * 64 + i * 16 + gid;
#pragma unroll
        for (int j = 0; j < 4; j++) {
            int c = n0 + wn * 32 + j * 8 + 2 * tq;
            *(float2*)(Cp + (size_t)r * HW + c)       = make_float2(acc[i][j][0], acc[i][j][1]);
            *(float2*)(Cp + (size_t)(r + 8) * HW + c) = make_float2(acc[i][j][2], acc[i][j][3]);
        }
    }
}

// ---------------- l2norm q (in place) + q_probe accumulation ---------------
__global__ void l2q_kernel() {
    int tx = threadIdx.x, ty = threadIdx.y;
    int bh = blockIdx.x >> 7;
    int pix = (blockIdx.x & 127) * 32 + tx;
    size_t base = (size_t)bh * 64 * HW + pix;

    float v[8]; float s = 0.f;
#pragma unroll
    for (int i = 0; i < 8; i++) {
        int d = ty + i * 8;
        v[i] = g_q[base + (size_t)d * HW];
        s += v[i] * v[i];
    }
    __shared__ float rs[8][32];
    rs[ty][tx] = s; __syncthreads();
    for (int st = 4; st > 0; st >>= 1) { if (ty < st) rs[ty][tx] += rs[ty + st][tx]; __syncthreads(); }
    float n = sqrtf(rs[0][tx]);
    float inv = 1.0f / fmaxf(n, 1e-12f);
#pragma unroll
    for (int i = 0; i < 8; i++) {
        int d = ty + i * 8;
        float qn = v[i] * inv;
        g_q[base + (size_t)d * HW] = qn;
        float r = qn;
#pragma unroll
        for (int o = 16; o > 0; o >>= 1) r += __shfl_down_sync(0xffffffffu, r, o);
        if (tx == 0) atomicAdd(&g_qprobe[bh * 64 + d], r);
    }
}

// ---------------- l2norm k (in place) + row/col |k| sums -------------------
__global__ void l2k_kernel() {
    int tx = threadIdx.x, ty = threadIdx.y;
    int bh = blockIdx.x >> 7;
    int pixb = (blockIdx.x & 127) * 32;
    int pix = pixb + tx;
    int b = bh >> 3, head = bh & 7;
    size_t cbase = (size_t)(b * 16 + head) * 64 * HW;
    int h = pix >> 6, w = pix & 63;

    float v[8]; float s = 0.f;
#pragma unroll
    for (int i = 0; i < 8; i++) {
        int d = ty + i * 8;
        v[i] = g_kv[cbase + (size_t)d * HW + pix];
        s += v[i] * v[i];
    }
    __shared__ float rs[8][32];
    rs[ty][tx] = s; __syncthreads();
    for (int st = 4; st > 0; st >>= 1) { if (ty < st) rs[ty][tx] += rs[ty + st][tx]; __syncthreads(); }
    float n = sqrtf(rs[0][tx]);
    float inv = 1.0f / fmaxf(n, 1e-12f);
#pragma unroll
    for (int i = 0; i < 8; i++) {
        int d = ty + i * 8;
        float kn = v[i] * inv;
        g_kv[cbase + (size_t)d * HW + pix] = kn;
        float a = fabsf(kn);
        float r = a;
#pragma unroll
        for (int o = 16; o > 0; o >>= 1) r += __shfl_down_sync(0xffffffffu, r, o);
        if (tx == 0) atomicAdd(&g_rowabs[bh * 4096 + d * 64 + h], r);
        atomicAdd(&g_colabs[bh * 4096 + d * 64 + w], a);
    }
}

// ---------------- scores + top-8 selection ---------------------------------
__global__ void score_kernel() {
    int bh = blockIdx.x;
    int t = threadIdx.x;
    __shared__ float qp[64], sc[64];
    qp[t] = g_qprobe[bh * 64 + t];
    __syncthreads();

    float s = 0.f;
    for (int d = 0; d < 64; d++) s += qp[d] * g_rowabs[bh * 4096 + d * 64 + t];
    sc[t] = s;
    __syncthreads();
    if (t == 0) {
        for (int it = 0; it < 8; it++) {
            int best = 0; float bv = sc[0];
            for (int h = 1; h < 64; h++) if (sc[h] > bv) { bv = sc[h]; best = h; }
            g_idxh[bh * 8 + it] = best; sc[best] = -3e38f;
        }
    }
    __syncthreads();

    float s2 = 0.f;
    for (int d = 0; d < 64; d++) s2 += qp[d] * g_colabs[bh * 4096 + d * 64 + t];
    sc[t] = s2;
    __syncthreads();
    if (t == 0) {
        for (int it = 0; it < 8; it++) {
            int best = 0; float bv = sc[0];
            for (int w = 1; w < 64; w++) if (sc[w] > bv) { bv = sc[w]; best = w; }
            g_idxw[bh * 8 + it] = best; sc[best] = -3e38f;
        }
    }
}

// ---------------- gather selected K/V into dense [bh][64][64] --------------
__global__ void gather_kernel() {
    int bh = blockIdx.x;
    int b = bh >> 3, head = bh & 7;
    size_t kc = (size_t)(b * 16 + head) * 64 * HW;
    size_t vc = (size_t)(b * 16 + 8 + head) * 64 * HW;
    __shared__ int ih[8], iw[8];
    if (threadIdx.x < 8) ih[threadIdx.x] = g_idxh[bh * 8 + threadIdx.x];
    else if (threadIdx.x < 16) iw[threadIdx.x - 8] = g_idxw[bh * 8 + threadIdx.x - 8];
    __syncthreads();
    for (int t = threadIdx.x; t < 4096; t += 256) {
        int j = t >> 6, d = t & 63;
        int r = j >> 3, c = j & 7;
        int pix = ih[r] * 64 + iw[c];
        g_ksel[bh * 4096 + t] = g_kv[kc + (size_t)d * HW + pix];
        g_vsel[bh * 4096 + t] = g_kv[vc + (size_t)d * HW + pix];
    }
}

// ---------------- attention: 4096 queries x 64 kv per head -----------------
__global__ void __launch_bounds__(128)
attn_kernel() {
    __shared__ float ks[64 * 64];
    __shared__ float vs[64 * 64];
    int bh = blockIdx.y;
    int pix = blockIdx.x * 128 + threadIdx.x;

    const float4* kg = (const float4*)&g_ksel[bh * 4096];
    const float4* vg = (const float4*)&g_vsel[bh * 4096];
    float4* ks4 = (float4*)ks; float4* vs4 = (float4*)vs;
    for (int i = threadIdx.x; i < 1024; i += 128) { ks4[i] = kg[i]; vs4[i] = vg[i]; }
    __syncthreads();

    size_t qb = (size_t)bh * 64 * HW + pix;
    float sim[64];
#pragma unroll
    for (int j = 0; j < 64; j++) sim[j] = 0.f;

    for (int dc = 0; dc < 64; dc += 16) {
        float q0[16];
#pragma unroll
        for (int i = 0; i < 16; i++) q0[i] = g_q[qb + (size_t)(dc + i) * HW];
#pragma unroll
        for (int j = 0; j < 64; j++) {
            const float4* kr = (const float4*)&ks[j * 64 + dc];
#pragma unroll
            for (int i4 = 0; i4 < 4; i4++) {
                float4 kvv = kr[i4];
                sim[j] += q0[i4*4+0]*kvv.x + q0[i4*4+1]*kvv.y
                        + q0[i4*4+2]*kvv.z + q0[i4*4+3]*kvv.w;
            }
        }
    }
    float mx = sim[0];
#pragma unroll
    for (int j = 1; j < 64; j++) mx = fmaxf(mx, sim[j]);
    float sum = 0.f;
#pragma unroll
    for (int j = 0; j < 64; j++) { sim[j] = __expf(sim[j] - mx); sum += sim[j]; }
    float invs = 1.0f / sum;

    size_t ob = (size_t)bh * 64 * HW + pix;
    for (int dc = 0; dc < 64; dc += 32) {
        float acc[32];
#pragma unroll
        for (int i = 0; i < 32; i++) acc[i] = 0.f;
#pragma unroll
        for (int j = 0; j < 64; j++) {
            const float4* vr = (const float4*)&vs[j * 64 + dc];
            float p = sim[j];
#pragma unroll
            for (int i4 = 0; i4 < 8; i4++) {
                float4 vv = vr[i4];
                acc[i4*4+0] += p * vv.x; acc[i4*4+1] += p * vv.y;
                acc[i4*4+2] += p * vv.z; acc[i4*4+3] += p * vv.w;
            }
        }
#pragma unroll
        for (int i = 0; i < 32; i++)
            g_att[ob + (size_t)(dc + i) * HW] = tf32r(acc[i] * invs);
    }
}

// ---------------- launch ----------------------------------------------------
extern "C" void kernel_launch(void* const* d_in, const int* in_sizes, int n_in,
                              void* d_out, int out_size) {
    const float* query_source = (const float*)d_in[0];
    const float* context      = (const float*)d_in[1];
    const float* cn_g = (const float*)d_in[2];
    const float* cn_b = (const float*)d_in[3];
    const float* qn_g = (const float*)d_in[4];
    const float* qn_b = (const float*)d_in[5];
    const float* on_g = (const float*)d_in[6];
    const float* on_b = (const float*)d_in[7];
    const float* w_kv  = (const float*)d_in[8];
    const float* w_q   = (const float*)d_in[9];
    const float* w_out = (const float*)d_in[10];
    const float* gamma = (const float*)d_in[11];
    float* out = (float*)d_out;

    dim3 lnb(32, 8);

    zero_kernel<<<1024, 256>>>();
    prep_w<<<512, 256>>>(w_kv, w_q, w_out);
    ln_kernel<<<1024, lnb>>>(context, cn_g, cn_b, 0);
    ln_kernel<<<1024, lnb>>>(query_source, qn_g, qn_b, 1);

    tgemm_kernel<<<dim3(32, 8, 8), 256>>>(1024, 256, 0);
    tgemm_kernel<<<dim3(32, 4, 8), 256>>>(512, 256, 1);

    l2q_kernel<<<8192, lnb>>>();
    l2k_kernel<<<8192, lnb>>>();

    score_kernel<<<64, 64>>>();
    gather_kernel<<<64, 256>>>();

    attn_kernel<<<dim3(32, 64), 128>>>();

    tgemm_kernel<<<dim3(32, 2, 8), 256>>>(256, 512, 2);

    final_kernel<<<1024, lnb>>>(query_source, on_g, on_b, gamma, out);
}

// round 6
// speedup vs baseline: 2.7186x; 1.2219x over previous
#include <cuda_runtime.h>
#include <math.h>
#include <stdint.h>

#define HW    4096
#define CDIM  256
#define BATCH 8
#define NBH   64     // B*HEADS
#define DH    64     // DIM_HEAD

// ---------------- scratch (device globals; no runtime allocation) ----------
__device__ float g_ctx[BATCH * CDIM * HW];        // layernormed context (tf32-rounded)
__device__ float g_qs [BATCH * CDIM * HW];        // layernormed query_source (tf32-rounded)
__device__ float g_kv [BATCH * 1024 * HW];        // w_kv output (k then v per batch)
__device__ float g_q  [BATCH * 512  * HW];        // w_q output (l2-normalized in place)
__device__ float g_att[BATCH * 512  * HW];        // attention output (tf32-rounded)
__device__ float g_y  [BATCH * CDIM * HW];        // w_out output
__device__ float g_qprobe[NBH * DH];
__device__ float g_rowabs[NBH * DH * 64];         // [bh][d][h]
__device__ float g_colabs[NBH * DH * 64];         // [bh][d][w]
__device__ int   g_idxh[NBH * 8];
__device__ int   g_idxw[NBH * 8];
__device__ float g_kselT[NBH * 64 * DH];          // [bh][d][j]  (K^T for mma)
__device__ float g_vsel [NBH * 64 * DH];          // [bh][j][d]

// tf32-pre-rounded weights, packed in mma-fragment order:
// [mtile128][kt16][mblk16][ks8][lane32] -> float4 {A[m][k],A[m+8][k],A[m][k+4],A[m+8][k+4]}
__device__ float g_wkvp[1024 * 256];
__device__ float g_wqp [512 * 256];
__device__ float g_woutp[256 * 512];

__device__ __forceinline__ float tf32r(float x) {
    uint32_t u;
    asm("cvt.rna.tf32.f32 %0, %1;" : "=r"(u) : "f"(x));
    return __uint_as_float(u);
}

// ---------------- zero scratch reductions ----------------------------------
__global__ void zero_kernel() {
    int i = blockIdx.x * 256 + threadIdx.x;
    if (i < NBH * DH) g_qprobe[i] = 0.f;
    if (i < NBH * DH * 64) { g_rowabs[i] = 0.f; g_colabs[i] = 0.f; }
}

// ---------------- weight prep: tf32-round + pack into fragment order -------
__global__ void prep_w(const float* __restrict__ wkv,
                       const float* __restrict__ wq,
                       const float* __restrict__ wout) {
    int fid = blockIdx.x * 256 + threadIdx.x;
    const float* W; float4* Dst; int K, rel;
    if (fid < 65536)      { W = wkv;  Dst = (float4*)g_wkvp;  K = 256; rel = fid; }
    else if (fid < 98304) { W = wq;   Dst = (float4*)g_wqp;   K = 256; rel = fid - 65536; }
    else                  { W = wout; Dst = (float4*)g_woutp; K = 512; rel = fid - 98304; }
    int KT = K >> 4;
    int per_mtile = KT * 512;
    int mtile = rel / per_mtile;
    int r2 = rel - mtile * per_mtile;
    int kt = r2 >> 9;
    int sub = r2 & 511;
    int mblk = (sub >> 6) & 7;
    int ks = (sub >> 5) & 1;
    int lane = sub & 31;
    int gid = lane >> 2, tq = lane & 3;
    int m = mtile * 128 + mblk * 16 + gid;
    int k = kt * 16 + ks * 8 + tq;
    float4 v;
    v.x = tf32r(W[(size_t)m * K + k]);
    v.y = tf32r(W[(size_t)(m + 8) * K + k]);
    v.z = tf32r(W[(size_t)m * K + k + 4]);
    v.w = tf32r(W[(size_t)(m + 8) * K + k + 4]);
    Dst[rel] = v;
}

// ---------------- channel layernorm (per pixel over 256 channels) ----------
__global__ void ln_kernel(const float* __restrict__ x,
                          const float* __restrict__ gw,
                          const float* __restrict__ bw,
                          int outsel) {
    float* out = outsel ? g_qs : g_ctx;
    int tx = threadIdx.x, ty = threadIdx.y;
    int gp = blockIdx.x * 32 + tx;
    int bidx = gp >> 12;
    int p = gp & (HW - 1);
    size_t base = (size_t)bidx * CDIM * HW + p;

    float vals[32];
    float s = 0.f, s2 = 0.f;
#pragma unroll
    for (int i = 0; i < 32; i++) {
        int c = ty + i * 8;
        float v = x[base + (size_t)c * HW];
        vals[i] = v; s += v; s2 += v * v;
    }
    __shared__ float rs[8][32], rs2[8][32];
    rs[ty][tx] = s; rs2[ty][tx] = s2;
    __syncthreads();
    for (int st = 4; st > 0; st >>= 1) {
        if (ty < st) { rs[ty][tx] += rs[ty + st][tx]; rs2[ty][tx] += rs2[ty + st][tx]; }
        __syncthreads();
    }
    float mean = rs[0][tx] * (1.0f / CDIM);
    float var  = rs2[0][tx] * (1.0f / CDIM) - mean * mean;
    float inv  = rsqrtf(var + 1e-5f);
#pragma unroll
    for (int i = 0; i < 32; i++) {
        int c = ty + i * 8;
        out[base + (size_t)c * HW] = tf32r((vals[i] - mean) * inv * gw[c] + bw[c]);
    }
}

// ---------------- final: LN(g_y) * gamma + query_source -> d_out -----------
__global__ void final_kernel(const float* __restrict__ qsrc,
                             const float* __restrict__ gw,
                             const float* __restrict__ bw,
                             const float* __restrict__ gamma,
                             float* __restrict__ out) {
    int tx = threadIdx.x, ty = threadIdx.y;
    int gp = blockIdx.x * 32 + tx;
    int bidx = gp >> 12;
    int p = gp & (HW - 1);
    size_t base = (size_t)bidx * CDIM * HW + p;

    float vals[32];
    float s = 0.f, s2 = 0.f;
#pragma unroll
    for (int i = 0; i < 32; i++) {
        int c = ty + i * 8;
        float v = g_y[base + (size_t)c * HW];
        vals[i] = v; s += v; s2 += v * v;
    }
    __shared__ float rs[8][32], rs2[8][32];
    rs[ty][tx] = s; rs2[ty][tx] = s2;
    __syncthreads();
    for (int st = 4; st > 0; st >>= 1) {
        if (ty < st) { rs[ty][tx] += rs[ty + st][tx]; rs2[ty][tx] += rs2[ty + st][tx]; }
        __syncthreads();
    }
    float mean = rs[0][tx] * (1.0f / CDIM);
    float var  = rs2[0][tx] * (1.0f / CDIM) - mean * mean;
    float inv  = rsqrtf(var + 1e-5f);
    float gm = gamma[0];
#pragma unroll
    for (int i = 0; i < 32; i++) {
        int c = ty + i * 8;
        float ln = (vals[i] - mean) * inv * gw[c] + bw[c];
        out[base + (size_t)c * HW] = gm * ln + qsrc[base + (size_t)c * HW];
    }
}

// ---------------- cp.async helpers -----------------------------------------
__device__ __forceinline__ void cpasync16(uint32_t smem, const void* g) {
    asm volatile("cp.async.cg.shared.global [%0], [%1], 16;\n" :: "r"(smem), "l"(g));
}
#define CP_COMMIT() asm volatile("cp.async.commit_group;\n" ::: "memory")
#define CP_WAIT1()  asm volatile("cp.async.wait_group 1;\n" ::: "memory")

// ---------------- tensor-core batched GEMM (tf32 mma.sync) -----------------
#define BS_STRIDE 136   // 128 + 8 pad (conflict-free B fragment loads)

__global__ void __launch_bounds__(256)
tgemm_kernel(int M, int K, int sel) {
    const uint4* Ap4; const float* Bp; float* Cp;
    if (sel == 0)      { Ap4 = (const uint4*)g_wkvp;  Bp = g_ctx; Cp = g_kv; }
    else if (sel == 1) { Ap4 = (const uint4*)g_wqp;   Bp = g_qs;  Cp = g_q;  }
    else               { Ap4 = (const uint4*)g_woutp; Bp = g_att; Cp = g_y;  }
    int KT = K >> 4;
    Bp += (size_t)blockIdx.z * K * HW;
    Cp += (size_t)blockIdx.z * M * HW;
    Ap4 += (size_t)blockIdx.y * (KT * 512);

    __shared__ __align__(16) uint4 As4[3][512];
    __shared__ __align__(16) float Bs[3][16][BS_STRIDE];

    int m0 = blockIdx.y * 128, n0 = blockIdx.x * 128;
    int tid = threadIdx.x;
    int wid = tid >> 5, lane = tid & 31;
    int wm = wid >> 2, wn = wid & 3;          // warp 2x4
    int gid = lane >> 2, tq = lane & 3;

    int bk = tid >> 4;
    int bn = (tid & 15) * 8;

    auto load_stage = [&](int s, int kt) {
        uint32_t adst = (uint32_t)__cvta_generic_to_shared(&As4[s][tid]);
        const uint4* asrc = Ap4 + kt * 512 + tid;
        cpasync16(adst, asrc);
        adst = (uint32_t)__cvta_generic_to_shared(&As4[s][tid + 256]);
        cpasync16(adst, asrc + 256);
        uint32_t bdst = (uint32_t)__cvta_generic_to_shared(&Bs[s][bk][bn]);
        const float* bsrc = Bp + (size_t)(kt * 16 + bk) * HW + n0 + bn;
        cpasync16(bdst, bsrc);
        cpasync16(bdst + 16, bsrc + 4);
    };

    float acc[4][4][4];
#pragma unroll
    for (int i = 0; i < 4; i++)
#pragma unroll
        for (int j = 0; j < 4; j++)
#pragma unroll
            for (int r = 0; r < 4; r++) acc[i][j][r] = 0.f;

    load_stage(0, 0); CP_COMMIT();
    load_stage(1, 1); CP_COMMIT();

    for (int kt = 0; kt < KT; kt++) {
        CP_WAIT1();
        __syncthreads();
        if (kt + 2 < KT) load_stage((kt + 2) % 3, kt + 2);
        CP_COMMIT();
        int s = kt % 3;

#pragma unroll
        for (int ks = 0; ks < 2; ks++) {
            int kk = ks * 8 + tq;
            uint4 af[4];
            uint32_t bf[4][2];
#pragma unroll
            for (int i = 0; i < 4; i++)
                af[i] = As4[s][(4 * wm + i) * 64 + ks * 32 + lane];
#pragma unroll
            for (int j = 0; j < 4; j++) {
                int c = wn * 32 + j * 8 + gid;
                bf[j][0] = __float_as_uint(Bs[s][kk][c]);
                bf[j][1] = __float_as_uint(Bs[s][kk + 4][c]);
            }
#pragma unroll
            for (int i = 0; i < 4; i++)
#pragma unroll
                for (int j = 0; j < 4; j++) {
                    asm volatile(
                        "mma.sync.aligned.m16n8k8.row.col.f32.tf32.tf32.f32 "
                        "{%0,%1,%2,%3}, {%4,%5,%6,%7}, {%8,%9}, {%0,%1,%2,%3};"
                        : "+f"(acc[i][j][0]), "+f"(acc[i][j][1]),
                          "+f"(acc[i][j][2]), "+f"(acc[i][j][3])
                        : "r"(af[i].x), "r"(af[i].y), "r"(af[i].z), "r"(af[i].w),
                          "r"(bf[j][0]), "r"(bf[j][1]));
                }
        }
    }

#pragma unroll
    for (int i = 0; i < 4; i++) {
        int r = m0 + wm * 64 + i * 16 + gid;
#pragma unroll
        for (int j = 0; j < 4; j++) {
            int c = n0 + wn * 32 + j * 8 + 2 * tq;
            *(float2*)(Cp + (size_t)r * HW + c)       = make_float2(acc[i][j][0], acc[i][j][1]);
            *(float2*)(Cp + (size_t)(r + 8) * HW + c) = make_float2(acc[i][j][2], acc[i][j][3]);
        }
    }
}

// ---------------- l2norm q (in place) + q_probe accumulation ---------------
__global__ void l2q_kernel() {
    int tx = threadIdx.x, ty = threadIdx.y;
    int bh = blockIdx.x >> 7;
    int pix = (blockIdx.x & 127) * 32 + tx;
    size_t base = (size_t)bh * 64 * HW + pix;

    float v[8]; float s = 0.f;
#pragma unroll
    for (int i = 0; i < 8; i++) {
        int d = ty + i * 8;
        v[i] = g_q[base + (size_t)d * HW];
        s += v[i] * v[i];
    }
    __shared__ float rs[8][32];
    rs[ty][tx] = s; __syncthreads();
    for (int st = 4; st > 0; st >>= 1) { if (ty < st) rs[ty][tx] += rs[ty + st][tx]; __syncthreads(); }
    float n = sqrtf(rs[0][tx]);
    float inv = 1.0f / fmaxf(n, 1e-12f);
#pragma unroll
    for (int i = 0; i < 8; i++) {
        int d = ty + i * 8;
        float qn = v[i] * inv;
        g_q[base + (size_t)d * HW] = qn;
        float r = qn;
#pragma unroll
        for (int o = 16; o > 0; o >>= 1) r += __shfl_down_sync(0xffffffffu, r, o);
        if (tx == 0) atomicAdd(&g_qprobe[bh * 64 + d], r);
    }
}

// ---------------- l2norm k (in place) + row/col |k| sums -------------------
__global__ void l2k_kernel() {
    int tx = threadIdx.x, ty = threadIdx.y;
    int bh = blockIdx.x >> 7;
    int pixb = (blockIdx.x & 127) * 32;
    int pix = pixb + tx;
    int b = bh >> 3, head = bh & 7;
    size_t cbase = (size_t)(b * 16 + head) * 64 * HW;
    int h = pix >> 6, w = pix & 63;

    float v[8]; float s = 0.f;
#pragma unroll
    for (int i = 0; i < 8; i++) {
        int d = ty + i * 8;
        v[i] = g_kv[cbase + (size_t)d * HW + pix];
        s += v[i] * v[i];
    }
    __shared__ float rs[8][32];
    rs[ty][tx] = s; __syncthreads();
    for (int st = 4; st > 0; st >>= 1) { if (ty < st) rs[ty][tx] += rs[ty + st][tx]; __syncthreads(); }
    float n = sqrtf(rs[0][tx]);
    float inv = 1.0f / fmaxf(n, 1e-12f);
#pragma unroll
    for (int i = 0; i < 8; i++) {
        int d = ty + i * 8;
        float kn = v[i] * inv;
        g_kv[cbase + (size_t)d * HW + pix] = kn;
        float a = fabsf(kn);
        float r = a;
#pragma unroll
        for (int o = 16; o > 0; o >>= 1) r += __shfl_down_sync(0xffffffffu, r, o);
        if (tx == 0) atomicAdd(&g_rowabs[bh * 4096 + d * 64 + h], r);
        atomicAdd(&g_colabs[bh * 4096 + d * 64 + w], a);
    }
}

// ---------------- scores + top-8 selection ---------------------------------
__global__ void score_kernel() {
    int bh = blockIdx.x;
    int t = threadIdx.x;
    __shared__ float qp[64], sc[64];
    qp[t] = g_qprobe[bh * 64 + t];
    __syncthreads();

    float s = 0.f;
    for (int d = 0; d < 64; d++) s += qp[d] * g_rowabs[bh * 4096 + d * 64 + t];
    sc[t] = s;
    __syncthreads();
    if (t == 0) {
        for (int it = 0; it < 8; it++) {
            int best = 0; float bv = sc[0];
            for (int h = 1; h < 64; h++) if (sc[h] > bv) { bv = sc[h]; best = h; }
            g_idxh[bh * 8 + it] = best; sc[best] = -3e38f;
        }
    }
    __syncthreads();

    float s2 = 0.f;
    for (int d = 0; d < 64; d++) s2 += qp[d] * g_colabs[bh * 4096 + d * 64 + t];
    sc[t] = s2;
    __syncthreads();
    if (t == 0) {
        for (int it = 0; it < 8; it++) {
            int best = 0; float bv = sc[0];
            for (int w = 1; w < 64; w++) if (sc[w] > bv) { bv = sc[w]; best = w; }
            g_idxw[bh * 8 + it] = best; sc[best] = -3e38f;
        }
    }
}

// ---------------- gather selected K/V: K^T [d][j], V [j][d] -----------------
__global__ void gather_kernel() {
    int bh = blockIdx.x;
    int b = bh >> 3, head = bh & 7;
    size_t kc = (size_t)(b * 16 + head) * 64 * HW;
    size_t vc = (size_t)(b * 16 + 8 + head) * 64 * HW;
    __shared__ int ih[8], iw[8];
    if (threadIdx.x < 8) ih[threadIdx.x] = g_idxh[bh * 8 + threadIdx.x];
    else if (threadIdx.x < 16) iw[threadIdx.x - 8] = g_idxw[bh * 8 + threadIdx.x - 8];
    __syncthreads();
    for (int t = threadIdx.x; t < 4096; t += 256) {
        int j = t >> 6, d = t & 63;
        int r = j >> 3, c = j & 7;
        int pix = ih[r] * 64 + iw[c];
        g_kselT[bh * 4096 + d * 64 + j] = g_kv[kc + (size_t)d * HW + pix];
        g_vsel [bh * 4096 + t]          = g_kv[vc + (size_t)d * HW + pix];
    }
}

// ---------------- tensor-core attention ------------------------------------
// one CTA per (bh, 128-pixel tile); 128 threads = 4 warps, 32 pix rows each.
// dynamic smem (floats): kst[64][72] | vs[64][72] | union(qs[64][136] / ps[128][68])
#define KT_ST 72
#define QS_ST 136
#define PS_ST 68
#define ATTN_SMEM_FLOATS (4608 + 4608 + 8704)

__global__ void __launch_bounds__(128)
attn_mma_kernel() {
    extern __shared__ float sm[];
    float* kst = sm;                  // [d][j]
    float* vs  = sm + 4608;           // [j][d]
    float* qps = sm + 9216;           // qs [d][pix] then ps [pix][j]

    int bh = blockIdx.y;
    int pix0 = blockIdx.x * 128;
    int tid = threadIdx.x, lane = tid & 31, w = tid >> 5;
    int gid = lane >> 2, tq = lane & 3;
    int m0w = w * 32;
    size_t qb = (size_t)bh * 64 * HW + pix0;

    // stage K^T and V (tf32-rounded)
    for (int t = tid; t < 4096; t += 128) {
        int r = t >> 6, c = t & 63;
        kst[r * KT_ST + c] = tf32r(g_kselT[bh * 4096 + t]);
        vs [r * KT_ST + c] = tf32r(g_vsel [bh * 4096 + t]);
    }
    // stage Q tile: qs[d][pix], 64 rows of 128
    for (int r = 0; r < 64; r += 2) {
        int rr = r + (tid >> 6);
        int cc = tid & 63;
        qps[rr * QS_ST + cc]      = tf32r(g_q[qb + (size_t)rr * HW + cc]);
        qps[rr * QS_ST + cc + 64] = tf32r(g_q[qb + (size_t)rr * HW + cc + 64]);
    }
    __syncthreads();

    // ---- S = Q K^T : per warp 2 m16 tiles x 8 n8 tiles, k = 64 ----
    float accs[2][8][4];
#pragma unroll
    for (int i = 0; i < 2; i++)
#pragma unroll
        for (int n = 0; n < 8; n++)
#pragma unroll
            for (int r = 0; r < 4; r++) accs[i][n][r] = 0.f;

#pragma unroll
    for (int k = 0; k < 8; k++) {
        int kk = k * 8;
        uint32_t a[2][4], b[8][2];
#pragma unroll
        for (int i = 0; i < 2; i++) {
            int mc = m0w + i * 16 + gid;
            a[i][0] = __float_as_uint(qps[(kk + tq) * QS_ST + mc]);
            a[i][1] = __float_as_uint(qps[(kk + tq) * QS_ST + mc + 8]);
            a[i][2] = __float_as_uint(qps[(kk + tq + 4) * QS_ST + mc]);
            a[i][3] = __float_as_uint(qps[(kk + tq + 4) * QS_ST + mc + 8]);
        }
#pragma unroll
        for (int n = 0; n < 8; n++) {
            b[n][0] = __float_as_uint(kst[(kk + tq) * KT_ST + n * 8 + gid]);
            b[n][1] = __float_as_uint(kst[(kk + tq + 4) * KT_ST + n * 8 + gid]);
        }
#pragma unroll
        for (int i = 0; i < 2; i++)
#pragma unroll
            for (int n = 0; n < 8; n++)
                asm volatile(
                    "mma.sync.aligned.m16n8k8.row.col.f32.tf32.tf32.f32 "
                    "{%0,%1,%2,%3}, {%4,%5,%6,%7}, {%8,%9}, {%0,%1,%2,%3};"
                    : "+f"(accs[i][n][0]), "+f"(accs[i][n][1]),
                      "+f"(accs[i][n][2]), "+f"(accs[i][n][3])
                    : "r"(a[i][0]), "r"(a[i][1]), "r"(a[i][2]), "r"(a[i][3]),
                      "r"(b[n][0]), "r"(b[n][1]));
    }

    // ---- softmax over j (64) per pix row; keep 1/sum, P unnormalized ----
    float inv0[2], inv1[2];
#pragma unroll
    for (int i = 0; i < 2; i++) {
        float mx0 = -3e38f, mx1 = -3e38f;
#pragma unroll
        for (int n = 0; n < 8; n++) {
            mx0 = fmaxf(mx0, fmaxf(accs[i][n][0], accs[i][n][1]));
            mx1 = fmaxf(mx1, fmaxf(accs[i][n][2], accs[i][n][3]));
        }
        mx0 = fmaxf(mx0, __shfl_xor_sync(0xffffffffu, mx0, 1));
        mx0 = fmaxf(mx0, __shfl_xor_sync(0xffffffffu, mx0, 2));
        mx1 = fmaxf(mx1, __shfl_xor_sync(0xffffffffu, mx1, 1));
        mx1 = fmaxf(mx1, __shfl_xor_sync(0xffffffffu, mx1, 2));
        float s0 = 0.f, s1 = 0.f;
#pragma unroll
        for (int n = 0; n < 8; n++) {
            accs[i][n][0] = __expf(accs[i][n][0] - mx0);
            accs[i][n][1] = __expf(accs[i][n][1] - mx0);
            accs[i][n][2] = __expf(accs[i][n][2] - mx1);
            accs[i][n][3] = __expf(accs[i][n][3] - mx1);
            s0 += accs[i][n][0] + accs[i][n][1];
            s1 += accs[i][n][2] + accs[i][n][3];
        }
        s0 += __shfl_xor_sync(0xffffffffu, s0, 1);
        s0 += __shfl_xor_sync(0xffffffffu, s0, 2);
        s1 += __shfl_xor_sync(0xffffffffu, s1, 1);
        s1 += __shfl_xor_sync(0xffffffffu, s1, 2);
        inv0[i] = 1.0f / s0;
        inv1[i] = 1.0f / s1;
    }

    // all warps done reading qs before overwriting union buffer with P
    __syncthreads();
    float* ps = qps;
#pragma unroll
    for (int i = 0; i < 2; i++) {
        int r0 = m0w + i * 16 + gid;
#pragma unroll
        for (int n = 0; n < 8; n++) {
            int c = n * 8 + 2 * tq;
            ps[r0 * PS_ST + c]           = tf32r(accs[i][n][0]);
            ps[r0 * PS_ST + c + 1]       = tf32r(accs[i][n][1]);
            ps[(r0 + 8) * PS_ST + c]     = tf32r(accs[i][n][2]);
            ps[(r0 + 8) * PS_ST + c + 1] = tf32r(accs[i][n][3]);
        }
    }
    // warp-local rows: no further sync needed

    // ---- O = P V : k = j (64), n = d (64) ----
    float acco[2][8][4];
#pragma unroll
    for (int i = 0; i < 2; i++)
#pragma unroll
        for (int n = 0; n < 8; n++)
#pragma unroll
            for (int r = 0; r < 4; r++) acco[i][n][r] = 0.f;

#pragma unroll
    for (int k = 0; k < 8; k++) {
        int kk = k * 8;
        uint32_t a[2][4], b[8][2];
#pragma unroll
        for (int i = 0; i < 2; i++) {
            int r0 = m0w + i * 16 + gid;
            a[i][0] = __float_as_uint(ps[r0 * PS_ST + kk + tq]);
            a[i][1] = __float_as_uint(ps[(r0 + 8) * PS_ST + kk + tq]);
            a[i][2] = __float_as_uint(ps[r0 * PS_ST + kk + tq + 4]);
            a[i][3] = __float_as_uint(ps[(r0 + 8) * PS_ST + kk + tq + 4]);
        }
#pragma unroll
        for (int n = 0; n < 8; n++) {
            b[n][0] = __float_as_uint(vs[(kk + tq) * KT_ST + n * 8 + gid]);
            b[n][1] = __float_as_uint(vs[(kk + tq + 4) * KT_ST + n * 8 + gid]);
        }
#pragma unroll
        for (int i = 0; i < 2; i++)
#pragma unroll
            for (int n = 0; n < 8; n++)
                asm volatile(
                    "mma.sync.aligned.m16n8k8.row.col.f32.tf32.tf32.f32 "
                    "{%0,%1,%2,%3}, {%4,%5,%6,%7}, {%8,%9}, {%0,%1,%2,%3};"
                    : "+f"(acco[i][n][0]), "+f"(acco[i][n][1]),
                      "+f"(acco[i][n][2]), "+f"(acco[i][n][3])
                    : "r"(a[i][0]), "r"(a[i][1]), "r"(a[i][2]), "r"(a[i][3]),
                      "r"(b[n][0]), "r"(b[n][1]));
    }

    // ---- write O with row scaling; g_att layout [bh*64 + d][pix] ----
    size_t ob = (size_t)bh * 64 * HW + pix0;
#pragma unroll
    for (int i = 0; i < 2; i++) {
        int prow = m0w + i * 16 + gid;
#pragma unroll
        for (int n = 0; n < 8; n++) {
            int d0 = n * 8 + 2 * tq;
            g_att[ob + (size_t)d0 * HW + prow]           = tf32r(acco[i][n][0] * inv0[i]);
            g_att[ob + (size_t)(d0 + 1) * HW + prow]     = tf32r(acco[i][n][1] * inv0[i]);
            g_att[ob + (size_t)d0 * HW + prow + 8]       = tf32r(acco[i][n][2] * inv1[i]);
            g_att[ob + (size_t)(d0 + 1) * HW + prow + 8] = tf32r(acco[i][n][3] * inv1[i]);
        }
    }
}

// ---------------- launch ----------------------------------------------------
extern "C" void kernel_launch(void* const* d_in, const int* in_sizes, int n_in,
                              void* d_out, int out_size) {
    const float* query_source = (const float*)d_in[0];
    const float* context      = (const float*)d_in[1];
    const float* cn_g = (const float*)d_in[2];
    const float* cn_b = (const float*)d_in[3];
    const float* qn_g = (const float*)d_in[4];
    const float* qn_b = (const float*)d_in[5];
    const float* on_g = (const float*)d_in[6];
    const float* on_b = (const float*)d_in[7];
    const float* w_kv  = (const float*)d_in[8];
    const float* w_q   = (const float*)d_in[9];
    const float* w_out = (const float*)d_in[10];
    const float* gamma = (const float*)d_in[11];
    float* out = (float*)d_out;

    dim3 lnb(32, 8);
    const int attn_smem = ATTN_SMEM_FLOATS * 4;   // 71680 B
    cudaFuncSetAttribute(attn_mma_kernel,
                         cudaFuncAttributeMaxDynamicSharedMemorySize, attn_smem);

    zero_kernel<<<1024, 256>>>();
    prep_w<<<512, 256>>>(w_kv, w_q, w_out);
    ln_kernel<<<1024, lnb>>>(context, cn_g, cn_b, 0);
    ln_kernel<<<1024, lnb>>>(query_source, qn_g, qn_b, 1);

    tgemm_kernel<<<dim3(32, 8, 8), 256>>>(1024, 256, 0);
    tgemm_kernel<<<dim3(32, 4, 8), 256>>>(512, 256, 1);

    l2q_kernel<<<8192, lnb>>>();
    l2k_kernel<<<8192, lnb>>>();

    score_kernel<<<64, 64>>>();
    gather_kernel<<<64, 256>>>();

    attn_mma_kernel<<<dim3(32, 64), 128, attn_smem>>>();

    tgemm_kernel<<<dim3(32, 2, 8), 256>>>(256, 512, 2);

    final_kernel<<<1024, lnb>>>(query_source, on_g, on_b, gamma, out);
}